// round 3
// baseline (speedup 1.0000x reference)
#include <cuda_runtime.h>
#include <math.h>

// Problem-size bounds (N=32768, K=8192, D=256 for this dataset)
#define N_MAX 32768
#define K_MAX 8192

// Scratch (no allocations allowed)
__device__ int    g_idx[N_MAX];
__device__ int    g_counts[K_MAX];
__device__ float  g_cnorm[K_MAX];   // 0.5 * ||c||^2
__device__ double g_loss;

__device__ __forceinline__ float warpReduceSum(float v) {
#pragma unroll
    for (int o = 16; o > 0; o >>= 1) v += __shfl_xor_sync(0xffffffffu, v, o);
    return v;
}

// ---------------------------------------------------------------------------
// Kernel 1: codebook half-norms + zero accumulators (replay-safe)
// grid = K/8 blocks x 256 threads (one warp per codebook row)
// ---------------------------------------------------------------------------
__global__ void vq_prep(const float* __restrict__ C) {
    int w = threadIdx.x >> 5, lane = threadIdx.x & 31;
    int row = blockIdx.x * 8 + w;
    const float4* p = (const float4*)(C + (size_t)row * 256);
    float s = 0.f;
#pragma unroll
    for (int i = 0; i < 2; i++) {
        float4 v = p[lane + 32 * i];
        s += v.x * v.x + v.y * v.y + v.z * v.z + v.w * v.w;
    }
    s = warpReduceSum(s);
    if (lane == 0) g_cnorm[row] = 0.5f * s;
    if (threadIdx.x < 8) g_counts[blockIdx.x * 8 + threadIdx.x] = 0;
    if (blockIdx.x == 0 && threadIdx.x == 0) g_loss = 0.0;
}

// ---------------------------------------------------------------------------
// Kernel 2: fused GEMM + argmax.  score(n,k) = x_n . c_k - 0.5||c_k||^2
// Tile: 128 rows x 64 codes, 256 threads, per-thread 8x4 packed f32x2 accs.
// ---------------------------------------------------------------------------
#define TN 128
#define TK 64

__global__ __launch_bounds__(256, 2) void vq_main(const float* __restrict__ X,
                                                  const float* __restrict__ C,
                                                  float* __restrict__ outTok,
                                                  int N, int K) {
    // smem staged as (even,odd) dim pairs for fma.rn.f32x2
    __shared__ float2 Xs[8][TN];       // [pair][row]
    __shared__ float2 Cs[8][TK];       // [pair][code]
    __shared__ float  Cn[TK];
    __shared__ float  sS[TN][17];
    __shared__ int    sI[TN][17];

    const int t  = threadIdx.x;
    const int tx = t & 15;             // col group: cols tx + 16*j
    const int ty = t >> 4;             // row group: rows ty + 16*i
    const int rowBase = blockIdx.x * TN;

    float best[8];
    int   bidx[8];
#pragma unroll
    for (int i = 0; i < 8; i++) { best[i] = -INFINITY; bidx[i] = 0; }

    const int xrow = t >> 1, xh = t & 1;       // 2 threads per X row, 8 dims each
    const int ccode = t >> 2, cseg = t & 3;    // 4 threads per C row, 4 dims each
    const float* Xbase = X + (size_t)(rowBase + xrow) * 256 + xh * 8;

    for (int k0 = 0; k0 < K; k0 += TK) {
        __syncthreads();               // prev epilogue done reading Cn / smem
        if (t < TK) Cn[t] = g_cnorm[k0 + t];

        unsigned long long acc[8][4];
#pragma unroll
        for (int i = 0; i < 8; i++)
#pragma unroll
            for (int j = 0; j < 4; j++) acc[i][j] = 0ull;

        const float* Cbase = C + (size_t)(k0 + ccode) * 256 + cseg * 4;

        for (int d0 = 0; d0 < 256; d0 += 16) {
            // issue global loads before the barrier for latency overlap
            float4 a = *(const float4*)(Xbase + d0);
            float4 b = *(const float4*)(Xbase + d0 + 4);
            float4 c = *(const float4*)(Cbase + d0);
            __syncthreads();           // previous chunk's compute done
            Xs[xh * 4 + 0][xrow] = make_float2(a.x, a.y);
            Xs[xh * 4 + 1][xrow] = make_float2(a.z, a.w);
            Xs[xh * 4 + 2][xrow] = make_float2(b.x, b.y);
            Xs[xh * 4 + 3][xrow] = make_float2(b.z, b.w);
            Cs[cseg * 2 + 0][ccode] = make_float2(c.x, c.y);
            Cs[cseg * 2 + 1][ccode] = make_float2(c.z, c.w);
            __syncthreads();

#pragma unroll
            for (int p = 0; p < 8; p++) {
                unsigned long long xf[8], cf[4];
#pragma unroll
                for (int i = 0; i < 8; i++)
                    xf[i] = *(const unsigned long long*)&Xs[p][ty + 16 * i];
#pragma unroll
                for (int j = 0; j < 4; j++)
                    cf[j] = *(const unsigned long long*)&Cs[p][tx + 16 * j];
#pragma unroll
                for (int i = 0; i < 8; i++)
#pragma unroll
                    for (int j = 0; j < 4; j++)
                        asm("fma.rn.f32x2 %0, %1, %2, %0;"
                            : "+l"(acc[i][j]) : "l"(xf[i]), "l"(cf[j]));
            }
        }

        // epilogue: score = lo+hi - 0.5||c||^2 ; running argmax, first-index ties
#pragma unroll
        for (int j = 0; j < 4; j++) {   // j ascending => global col ascending
            int col = tx + 16 * j;
            float cn = Cn[col];
#pragma unroll
            for (int i = 0; i < 8; i++) {
                float lo, hi;
                asm("mov.b64 {%0,%1}, %2;" : "=f"(lo), "=f"(hi) : "l"(acc[i][j]));
                float s = lo + hi - cn;
                if (s > best[i]) { best[i] = s; bidx[i] = k0 + col; }
            }
        }
    }

    // cross-thread reduce over the 16 col-groups per row
    __syncthreads();
#pragma unroll
    for (int i = 0; i < 8; i++) {
        sS[ty + 16 * i][tx] = best[i];
        sI[ty + 16 * i][tx] = bidx[i];
    }
    __syncthreads();
    if (t < TN) {
        float b = sS[t][0]; int bi = sI[t][0];
#pragma unroll
        for (int x = 1; x < 16; x++) {
            float s = sS[t][x]; int si = sI[t][x];
            if (s > b || (s == b && si < bi)) { b = s; bi = si; }
        }
        int gr = rowBase + t;
        g_idx[gr]  = bi;
        outTok[gr] = (float)bi;
        atomicAdd(&g_counts[bi], 1);
    }
}

// ---------------------------------------------------------------------------
// Kernel 3: gather quantized rows, write straight-through output, sum (q-x)^2
// block = 256 threads -> 4 rows (64 threads/row, float4 lanes)
// ---------------------------------------------------------------------------
__global__ void vq_gather(const float* __restrict__ X, const float* __restrict__ C,
                          float* __restrict__ outQ) {
    int row  = blockIdx.x * 4 + (threadIdx.x >> 6);
    int lane = threadIdx.x & 63;
    int idx = g_idx[row];
    float4 qv = ((const float4*)(C + (size_t)idx * 256))[lane];
    float4 xv = ((const float4*)(X + (size_t)row * 256))[lane];
    float dx = qv.x - xv.x, dy = qv.y - xv.y, dz = qv.z - xv.z, dw = qv.w - xv.w;
    float4 o = make_float4(xv.x + dx, xv.y + dy, xv.z + dz, xv.w + dw);
    ((float4*)(outQ + (size_t)row * 256))[lane] = o;

    float s = dx * dx + dy * dy + dz * dz + dw * dw;
    s = warpReduceSum(s);
    __shared__ float ps[8];
    int w = threadIdx.x >> 5, ln = threadIdx.x & 31;
    if (ln == 0) ps[w] = s;
    __syncthreads();
    if (w == 0) {
        float v = (ln < 8) ? ps[ln] : 0.f;
        v = warpReduceSum(v);
        if (ln == 0) atomicAdd(&g_loss, (double)v);
    }
}

// ---------------------------------------------------------------------------
// Kernel 4: losses + perplexity, single block
// ---------------------------------------------------------------------------
__global__ void vq_fin(float* __restrict__ outScal, int N, int K) {
    double ent = 0.0;
    float invN = 1.0f / (float)N;
    for (int k = threadIdx.x; k < K; k += 256) {
        float p = (float)g_counts[k] * invN;
        ent += (double)(p * logf(p + 1e-10f));
    }
    __shared__ double ds[256];
    ds[threadIdx.x] = ent;
    __syncthreads();
    for (int s = 128; s > 0; s >>= 1) {
        if (threadIdx.x < s) ds[threadIdx.x] += ds[threadIdx.x + s];
        __syncthreads();
    }
    if (threadIdx.x == 0) {
        float perp = expf(-(float)ds[0]);
        double l = g_loss / ((double)N * 256.0);
        float lf = (float)l;
        outScal[0] = 1.25f * lf;   // vq_loss
        outScal[1] = 0.25f * lf;   // commitment_loss
        outScal[2] = lf;           // codebook_loss
        outScal[3] = perp;         // perplexity
    }
}

// ---------------------------------------------------------------------------
extern "C" void kernel_launch(void* const* d_in, const int* in_sizes, int n_in,
                              void* d_out, int out_size) {
    const float* X = (const float*)d_in[0];   // inputs  [32,1024,256] f32
    const float* C = (const float*)d_in[1];   // codebook [8192,256]  f32
    float* out = (float*)d_out;

    int N = in_sizes[0] / 256;   // 32768 rows
    int K = in_sizes[1] / 256;   // 8192 codes

    float* outTok  = out + (size_t)N * 256;      // tokens region
    float* outScal = outTok + N;                 // 4 scalars

    vq_prep<<<K / 8, 256>>>(C);
    vq_main<<<N / TN, 256>>>(X, C, outTok, N, K);
    vq_gather<<<N / 4, 256>>>(X, C, out);
    vq_fin<<<1, 256>>>(outScal, N, K);
}

// round 8
// speedup vs baseline: 2.6200x; 2.6200x over previous
#include <cuda_runtime.h>
#include <cuda_fp16.h>
#include <math.h>
#include <stdint.h>

// Problem sizes (fixed for this dataset)
#define N_ROWS  32768
#define K_CODES 8192
#define D_DIM   256
#define KEFF    768          // 3*256: [x1|x1|x2] . [c1|c2|c1]

// smem staging
#define PADK    40           // fp16 elems per smem row (32 data + 8 pad) = 80B
#define A_ST    (128 * PADK * 2)      // 10240 B
#define B_ST    (256 * PADK * 2)      // 20480 B
#define STAGE_B (A_ST + B_ST)         // 30720 B
#define NST     4
#define SMEM_STAGES (NST * STAGE_B)   // 122880
#define SMEM_RED    (128 * 4 * 4 * 2) // sBest + sIdx = 4096
#define SMEM_TOTAL  (SMEM_STAGES + SMEM_RED)

// -------- scratch (no allocations allowed) --------
__device__ int    g_idx[N_ROWS];
__device__ int    g_counts[K_CODES];
__device__ float  g_cnorm[K_CODES];            // 0.5*||c||^2
__device__ double g_loss;
__device__ __half g_Ah[(size_t)N_ROWS * KEFF]; // 50.3 MB
__device__ __half g_Bh[(size_t)K_CODES * KEFF];// 12.6 MB

// ======================= helpers =======================
__device__ __forceinline__ uint32_t smem_to_u32(const void* p) {
    uint32_t a;
    asm("{ .reg .u64 t; cvta.to.shared.u64 t, %1; cvt.u32.u64 %0, t; }" : "=r"(a) : "l"(p));
    return a;
}
__device__ __forceinline__ float warpReduceSum(float v) {
#pragma unroll
    for (int o = 16; o > 0; o >>= 1) v += __shfl_xor_sync(0xffffffffu, v, o);
    return v;
}

#define CP_ASYNC16(smem_u32, gptr) \
    asm volatile("cp.async.cg.shared.global [%0], [%1], 16;" :: "r"(smem_u32), "l"(gptr) : "memory")
#define CP_COMMIT() asm volatile("cp.async.commit_group;" ::: "memory")
#define CP_WAIT2()  asm volatile("cp.async.wait_group 2;" ::: "memory")

#define LDSM_X4(r0, r1, r2, r3, addr) \
    asm volatile("ldmatrix.sync.aligned.m8n8.x4.shared.b16 {%0,%1,%2,%3}, [%4];" \
        : "=r"(r0), "=r"(r1), "=r"(r2), "=r"(r3) : "r"(addr))
#define LDSM_X2(r0, r1, addr) \
    asm volatile("ldmatrix.sync.aligned.m8n8.x2.shared.b16 {%0,%1}, [%2];" \
        : "=r"(r0), "=r"(r1) : "r"(addr))

#define MMA16816(d, a, b) \
    asm volatile("mma.sync.aligned.m16n8k16.row.col.f32.f16.f16.f32 " \
        "{%0,%1,%2,%3},{%4,%5,%6,%7},{%8,%9},{%0,%1,%2,%3};" \
        : "+f"((d)[0]), "+f"((d)[1]), "+f"((d)[2]), "+f"((d)[3]) \
        : "r"((a)[0]), "r"((a)[1]), "r"((a)[2]), "r"((a)[3]), "r"((b)[0]), "r"((b)[1]))

// ---------------------------------------------------------------------------
// Prep A: fp16 split, row layout [0:256]=x1, [256:512]=x1, [512:768]=x2
// one warp per input row
// ---------------------------------------------------------------------------
__global__ void vq_prep_a(const float* __restrict__ X) {
    int w = threadIdx.x >> 5, lane = threadIdx.x & 31;
    int row = blockIdx.x * 8 + w;
    const float* x = X + (size_t)row * D_DIM;
    __half* a = g_Ah + (size_t)row * KEFF;
#pragma unroll
    for (int i = 0; i < 8; i++) {
        int c = lane + 32 * i;
        float v = x[c];
        __half hi = __float2half_rn(v);
        __half lo = __float2half_rn(v - __half2float(hi));
        a[c] = hi; a[256 + c] = hi; a[512 + c] = lo;
    }
}

// ---------------------------------------------------------------------------
// Prep B: [0:256]=c1, [256:512]=c2, [512:768]=c1 ; g_cnorm = 0.5||c||^2
// Also zero histogram + loss (replay-safe: runs each launch inside the graph).
// ---------------------------------------------------------------------------
__global__ void vq_prep_b(const float* __restrict__ C) {
    int w = threadIdx.x >> 5, lane = threadIdx.x & 31;
    int row = blockIdx.x * 8 + w;
    const float* c = C + (size_t)row * D_DIM;
    __half* b = g_Bh + (size_t)row * KEFF;
    float s = 0.f;
#pragma unroll
    for (int i = 0; i < 8; i++) {
        int k = lane + 32 * i;
        float v = c[k];
        s += v * v;
        __half hi = __float2half_rn(v);
        __half lo = __float2half_rn(v - __half2float(hi));
        b[k] = hi; b[256 + k] = lo; b[512 + k] = hi;
    }
    s = warpReduceSum(s);
    if (lane == 0) g_cnorm[row] = 0.5f * s;
    if (blockIdx.x < K_CODES / 256) g_counts[blockIdx.x * 256 + threadIdx.x] = 0;
    if (blockIdx.x == 0 && threadIdx.x == 0) g_loss = 0.0;
}

// ---------------------------------------------------------------------------
// Main: fp16x3 mma.sync GEMM, CTA = 128 rows x full code sweep (32 tiles of
// 256), fused per-row argmax.  8 warps in 2(M) x 4(N) grid, warp tile 64x64.
// 4-stage cp.async pipeline, K-chunks of 32 (2 k16 mma steps per chunk).
// ---------------------------------------------------------------------------
#define NTILES  32            // 8192 / 256
#define KCHUNK  24            // 768 / 32
#define TOTALCH (NTILES * KCHUNK)

__global__ void __launch_bounds__(256, 1) vq_main(float* __restrict__ outTok) {
    extern __shared__ char smem[];
    const uint32_t sbase = smem_to_u32(smem);
    float* sBest = (float*)(smem + SMEM_STAGES);
    int*   sIdx  = (int*)(smem + SMEM_STAGES + 128 * 4 * 4);

    const int tid  = threadIdx.x;
    const int lane = tid & 31;
    const int wid  = tid >> 5;
    const int warp_m = wid & 1;        // 0..1  -> rows warp_m*64
    const int warp_n = wid >> 1;       // 0..3  -> cols warp_n*64
    const int rowBase = blockIdx.x * 128;

    float acc[4][8][4];
#pragma unroll
    for (int i = 0; i < 4; i++)
#pragma unroll
        for (int j = 0; j < 8; j++)
#pragma unroll
            for (int r = 0; r < 4; r++) acc[i][j][r] = 0.f;

    float best[8];
    int   bidx[8];
#pragma unroll
    for (int r = 0; r < 8; r++) { best[r] = -INFINITY; bidx[r] = 0; }

    // producer: 6 cp.async.16B per thread per chunk (A:512 ops, B:1024 ops)
    auto issue_load = [&](int g) {
        if (g < TOTALCH) {
            int ct = g / KCHUNK, kc = g % KCHUNK, st = g & (NST - 1);
            uint32_t sa = sbase + st * STAGE_B;
            uint32_t sb = sa + A_ST;
            int kbase = kc * 32;
#pragma unroll
            for (int r = 0; r < 2; r++) {               // A: 128 rows x 64B
                int id = tid + 256 * r;                 // 0..511
                int row = id >> 2, seg = id & 3;
                uint32_t so = sa + row * (PADK * 2) + seg * 16;
                const __half* gp = g_Ah + (size_t)(rowBase + row) * KEFF + kbase + seg * 8;
                CP_ASYNC16(so, gp);
            }
#pragma unroll
            for (int r = 0; r < 4; r++) {               // B: 256 rows x 64B
                int id = tid + 256 * r;                 // 0..1023
                int row = id >> 2, seg = id & 3;
                uint32_t so = sb + row * (PADK * 2) + seg * 16;
                const __half* gp = g_Bh + (size_t)(ct * 256 + row) * KEFF + kbase + seg * 8;
                CP_ASYNC16(so, gp);
            }
        }
        CP_COMMIT();   // empty groups keep wait_group accounting uniform
    };

    issue_load(0); issue_load(1); issue_load(2);

    // ldmatrix base offsets (within a stage)
    const int l15 = lane & 15;
    const uint32_t aOff = (uint32_t)((warp_m * 64 + (lane & 15)) * (PADK * 2) + ((lane >> 4) * 8) * 2);
    const uint32_t bOff = (uint32_t)(A_ST + (warp_n * 64 + (l15 & 7)) * (PADK * 2) + ((l15 >> 3) * 8) * 2);

    int g = 0;
    for (int ct = 0; ct < NTILES; ct++) {
        for (int kc = 0; kc < KCHUNK; kc++, g++) {
            CP_WAIT2();
            __syncthreads();
            issue_load(g + 3);

            uint32_t stg = sbase + (uint32_t)(g & (NST - 1)) * STAGE_B;
#pragma unroll
            for (int ks = 0; ks < 2; ks++) {
                uint32_t areg[4][4], breg[8][2];
#pragma unroll
                for (int i = 0; i < 4; i++)
                    LDSM_X4(areg[i][0], areg[i][1], areg[i][2], areg[i][3],
                            stg + aOff + i * (16 * PADK * 2) + ks * 32);
#pragma unroll
                for (int j = 0; j < 8; j++)
                    LDSM_X2(breg[j][0], breg[j][1],
                            stg + bOff + j * (8 * PADK * 2) + ks * 32);
#pragma unroll
                for (int i = 0; i < 4; i++)
#pragma unroll
                    for (int j = 0; j < 8; j++)
                        MMA16816(acc[i][j], areg[i], breg[j]);
            }
        }

        // -------- epilogue for this 256-code tile: running argmax ---------
        int colq = (lane & 3) * 2;
#pragma unroll
        for (int j = 0; j < 8; j++) {
            int col = ct * 256 + warp_n * 64 + j * 8 + colq;
            float2 cn = *(const float2*)&g_cnorm[col];
#pragma unroll
            for (int i = 0; i < 4; i++) {
#pragma unroll
                for (int h = 0; h < 2; h++) {
                    int r = i * 2 + h;
                    float s0 = acc[i][j][h * 2 + 0] - cn.x;
                    float s1 = acc[i][j][h * 2 + 1] - cn.y;
                    if (s0 > best[r]) { best[r] = s0; bidx[r] = col; }
                    if (s1 > best[r]) { best[r] = s1; bidx[r] = col + 1; }
                    acc[i][j][h * 2 + 0] = 0.f;
                    acc[i][j][h * 2 + 1] = 0.f;
                }
            }
        }
    }

    // -------- final reduce: cols within warp (lane%4), then across N-warps
#pragma unroll
    for (int r = 0; r < 8; r++) {
        float b = best[r]; int ix = bidx[r];
#pragma unroll
        for (int off = 1; off <= 2; off <<= 1) {
            float ob = __shfl_xor_sync(0xffffffffu, b, off);
            int   oi = __shfl_xor_sync(0xffffffffu, ix, off);
            if (ob > b || (ob == b && oi < ix)) { b = ob; ix = oi; }
        }
        if ((lane & 3) == 0) {
            int i = r >> 1, h = r & 1;
            int row = warp_m * 64 + i * 16 + h * 8 + (lane >> 2);
            sBest[row * 4 + warp_n] = b;
            sIdx[row * 4 + warp_n]  = ix;
        }
    }
    __syncthreads();
    if (tid < 128) {
        float b = sBest[tid * 4 + 0]; int ix = sIdx[tid * 4 + 0];
#pragma unroll
        for (int w = 1; w < 4; w++) {
            float s = sBest[tid * 4 + w]; int si = sIdx[tid * 4 + w];
            if (s > b || (s == b && si < ix)) { b = s; ix = si; }
        }
        int gr = rowBase + tid;
        g_idx[gr]  = ix;
        outTok[gr] = (float)ix;
        atomicAdd(&g_counts[ix], 1);
    }
}

// ---------------------------------------------------------------------------
// Gather: quantized rows + straight-through output + sum (q-x)^2
// ---------------------------------------------------------------------------
__global__ void vq_gather(const float* __restrict__ X, const float* __restrict__ C,
                          float* __restrict__ outQ) {
    int row  = blockIdx.x * 4 + (threadIdx.x >> 6);
    int lane = threadIdx.x & 63;
    int idx = g_idx[row];
    float4 qv = ((const float4*)(C + (size_t)idx * D_DIM))[lane];
    float4 xv = ((const float4*)(X + (size_t)row * D_DIM))[lane];
    float dx = qv.x - xv.x, dy = qv.y - xv.y, dz = qv.z - xv.z, dw = qv.w - xv.w;
    ((float4*)(outQ + (size_t)row * D_DIM))[lane] =
        make_float4(xv.x + dx, xv.y + dy, xv.z + dz, xv.w + dw);

    float s = dx * dx + dy * dy + dz * dz + dw * dw;
    s = warpReduceSum(s);
    __shared__ float ps[8];
    int w = threadIdx.x >> 5, ln = threadIdx.x & 31;
    if (ln == 0) ps[w] = s;
    __syncthreads();
    if (w == 0) {
        float v = (ln < 8) ? ps[ln] : 0.f;
        v = warpReduceSum(v);
        if (ln == 0) atomicAdd(&g_loss, (double)v);
    }
}

// ---------------------------------------------------------------------------
// Finalize: losses + perplexity
// ---------------------------------------------------------------------------
__global__ void vq_fin(float* __restrict__ outScal) {
    double ent = 0.0;
    float invN = 1.0f / (float)N_ROWS;
    for (int k = threadIdx.x; k < K_CODES; k += 256) {
        float p = (float)g_counts[k] * invN;
        ent += (double)(p * logf(p + 1e-10f));
    }
    __shared__ double ds[256];
    ds[threadIdx.x] = ent;
    __syncthreads();
    for (int s = 128; s > 0; s >>= 1) {
        if (threadIdx.x < s) ds[threadIdx.x] += ds[threadIdx.x + s];
        __syncthreads();
    }
    if (threadIdx.x == 0) {
        float perp = expf(-(float)ds[0]);
        double l = g_loss / ((double)N_ROWS * (double)D_DIM);
        float lf = (float)l;
        outScal[0] = 1.25f * lf;   // vq_loss
        outScal[1] = 0.25f * lf;   // commitment_loss
        outScal[2] = lf;           // codebook_loss
        outScal[3] = perp;         // perplexity
    }
}

// ---------------------------------------------------------------------------
extern "C" void kernel_launch(void* const* d_in, const int* in_sizes, int n_in,
                              void* d_out, int out_size) {
    const float* X = (const float*)d_in[0];   // [32,1024,256] f32
    const float* C = (const float*)d_in[1];   // [8192,256]    f32
    float* out = (float*)d_out;

    float* outTok  = out + (size_t)N_ROWS * D_DIM;
    float* outScal = outTok + N_ROWS;

    cudaFuncSetAttribute(vq_main, cudaFuncAttributeMaxDynamicSharedMemorySize, SMEM_TOTAL);

    vq_prep_b<<<K_CODES / 8, 256>>>(C);
    vq_prep_a<<<N_ROWS / 8, 256>>>(X);
    vq_main<<<N_ROWS / 128, 256, SMEM_TOTAL>>>(outTok);
    vq_gather<<<N_ROWS / 4, 256>>>(X, C, out);
    vq_fin<<<1, 256>>>(outScal);
}

// round 11
// speedup vs baseline: 5.2375x; 1.9991x over previous
#include <cuda_runtime.h>
#include <cuda_fp16.h>
#include <math.h>
#include <stdint.h>

// Problem sizes (fixed for this dataset)
#define N_ROWS  32768
#define K_CODES 8192
#define D_DIM   256

// smem staging (K-chunks of 32 fp16)
#define PADK    40           // fp16 elems per smem row (32 data + 8 pad) = 80B
#define A_ST    (128 * PADK * 2)      // 10240 B
#define B_ST    (256 * PADK * 2)      // 20480 B
#define STAGE_B (A_ST + B_ST)         // 30720 B
#define NST     4
#define SMEM_STAGES (NST * STAGE_B)   // 122880
#define SMEM_RED    (128 * 4 * 16)    // top-2 reduce: 4 fields x 4B  = 8192
#define SMEM_TOTAL  (SMEM_STAGES + SMEM_RED)

// -------- scratch (no allocations allowed) --------
__device__ int    g_c1[N_ROWS];                 // approx best candidate
__device__ int    g_c2[N_ROWS];                 // approx runner-up
__device__ int    g_counts[K_CODES];
__device__ float  g_cnorm[K_CODES];             // 0.5*||c||^2 (fp32 exact-ish)
__device__ double g_loss;
__device__ __half g_Ah[(size_t)N_ROWS * D_DIM]; // 16.8 MB (x rounded to fp16)
__device__ __half g_Bh[(size_t)K_CODES * D_DIM];// 4.2 MB  (c rounded to fp16)

// ======================= helpers =======================
__device__ __forceinline__ uint32_t smem_to_u32(const void* p) {
    uint32_t a;
    asm("{ .reg .u64 t; cvta.to.shared.u64 t, %1; cvt.u32.u64 %0, t; }" : "=r"(a) : "l"(p));
    return a;
}
__device__ __forceinline__ float warpReduceSum(float v) {
#pragma unroll
    for (int o = 16; o > 0; o >>= 1) v += __shfl_xor_sync(0xffffffffu, v, o);
    return v;
}

#define CP_ASYNC16(smem_u32, gptr) \
    asm volatile("cp.async.cg.shared.global [%0], [%1], 16;" :: "r"(smem_u32), "l"(gptr) : "memory")
#define CP_COMMIT() asm volatile("cp.async.commit_group;" ::: "memory")
#define CP_WAIT2()  asm volatile("cp.async.wait_group 2;" ::: "memory")

#define LDSM_X4(r0, r1, r2, r3, addr) \
    asm volatile("ldmatrix.sync.aligned.m8n8.x4.shared.b16 {%0,%1,%2,%3}, [%4];" \
        : "=r"(r0), "=r"(r1), "=r"(r2), "=r"(r3) : "r"(addr))
#define LDSM_X2(r0, r1, addr) \
    asm volatile("ldmatrix.sync.aligned.m8n8.x2.shared.b16 {%0,%1}, [%2];" \
        : "=r"(r0), "=r"(r1) : "r"(addr))

#define MMA16816(d, a, b) \
    asm volatile("mma.sync.aligned.m16n8k16.row.col.f32.f16.f16.f32 " \
        "{%0,%1,%2,%3},{%4,%5,%6,%7},{%8,%9},{%0,%1,%2,%3};" \
        : "+f"((d)[0]), "+f"((d)[1]), "+f"((d)[2]), "+f"((d)[3]) \
        : "r"((a)[0]), "r"((a)[1]), "r"((a)[2]), "r"((a)[3]), "r"((b)[0]), "r"((b)[1]))

// ---------------------------------------------------------------------------
// Prep A: round inputs to fp16 (approx operand).  One warp per row.
// ---------------------------------------------------------------------------
__global__ void vq_prep_a(const float* __restrict__ X) {
    int w = threadIdx.x >> 5, lane = threadIdx.x & 31;
    int row = blockIdx.x * 8 + w;
    const float* x = X + (size_t)row * D_DIM;
    __half* a = g_Ah + (size_t)row * D_DIM;
#pragma unroll
    for (int i = 0; i < 8; i++) {
        int c = lane + 32 * i;
        a[c] = __float2half_rn(x[c]);
    }
}

// ---------------------------------------------------------------------------
// Prep B: fp16 codebook + fp32 half-norms; zero counts/loss (replay-safe).
// ---------------------------------------------------------------------------
__global__ void vq_prep_b(const float* __restrict__ C) {
    int w = threadIdx.x >> 5, lane = threadIdx.x & 31;
    int row = blockIdx.x * 8 + w;
    const float* c = C + (size_t)row * D_DIM;
    __half* b = g_Bh + (size_t)row * D_DIM;
    float s = 0.f;
#pragma unroll
    for (int i = 0; i < 8; i++) {
        int k = lane + 32 * i;
        float v = c[k];
        s += v * v;
        b[k] = __float2half_rn(v);
    }
    s = warpReduceSum(s);
    if (lane == 0) g_cnorm[row] = 0.5f * s;
    if (blockIdx.x < K_CODES / 256) g_counts[blockIdx.x * 256 + threadIdx.x] = 0;
    if (blockIdx.x == 0 && threadIdx.x == 0) g_loss = 0.0;
}

// ---------------------------------------------------------------------------
// Main: fp16 approx GEMM (K=256), CTA = 128 rows x 8192 codes (32 tiles of
// 256), fused per-row TOP-2 tracking.  8 warps 2(M) x 4(N), warp tile 64x64.
// ---------------------------------------------------------------------------
#define NTILES  32            // 8192 / 256
#define KCHUNK  8             // 256 / 32
#define TOTALCH (NTILES * KCHUNK)

__global__ void __launch_bounds__(256, 1) vq_main() {
    extern __shared__ char smem[];
    const uint32_t sbase = smem_to_u32(smem);
    float* sB1 = (float*)(smem + SMEM_STAGES);
    int*   sI1 = (int*)  (smem + SMEM_STAGES + 2048);
    float* sB2 = (float*)(smem + SMEM_STAGES + 4096);
    int*   sI2 = (int*)  (smem + SMEM_STAGES + 6144);

    const int tid  = threadIdx.x;
    const int lane = tid & 31;
    const int wid  = tid >> 5;
    const int warp_m = wid & 1;        // rows warp_m*64
    const int warp_n = wid >> 1;       // cols warp_n*64
    const int rowBase = blockIdx.x * 128;

    float acc[4][8][4];
#pragma unroll
    for (int i = 0; i < 4; i++)
#pragma unroll
        for (int j = 0; j < 8; j++)
#pragma unroll
            for (int r = 0; r < 4; r++) acc[i][j][r] = 0.f;

    float b1[8], b2[8];
    int   i1[8], i2[8];
#pragma unroll
    for (int r = 0; r < 8; r++) { b1[r] = b2[r] = -INFINITY; i1[r] = 0; i2[r] = 1; }

    // producer: A 512 x16B ops, B 1024 x16B ops per chunk
    auto issue_load = [&](int g) {
        if (g < TOTALCH) {
            int ct = g / KCHUNK, kc = g % KCHUNK, st = g & (NST - 1);
            uint32_t sa = sbase + st * STAGE_B;
            uint32_t sb = sa + A_ST;
            int kbase = kc * 32;
#pragma unroll
            for (int r = 0; r < 2; r++) {               // A: 128 rows x 64B
                int id = tid + 256 * r;
                int row = id >> 2, seg = id & 3;
                uint32_t so = sa + row * (PADK * 2) + seg * 16;
                const __half* gp = g_Ah + (size_t)(rowBase + row) * D_DIM + kbase + seg * 8;
                CP_ASYNC16(so, gp);
            }
#pragma unroll
            for (int r = 0; r < 4; r++) {               // B: 256 rows x 64B
                int id = tid + 256 * r;
                int row = id >> 2, seg = id & 3;
                uint32_t so = sb + row * (PADK * 2) + seg * 16;
                const __half* gp = g_Bh + (size_t)(ct * 256 + row) * D_DIM + kbase + seg * 8;
                CP_ASYNC16(so, gp);
            }
        }
        CP_COMMIT();
    };

    issue_load(0); issue_load(1); issue_load(2);

    const int l15 = lane & 15;
    const uint32_t aOff = (uint32_t)((warp_m * 64 + (lane & 15)) * (PADK * 2) + ((lane >> 4) * 8) * 2);
    const uint32_t bOff = (uint32_t)(A_ST + (warp_n * 64 + (l15 & 7)) * (PADK * 2) + ((l15 >> 3) * 8) * 2);

    int g = 0;
    for (int ct = 0; ct < NTILES; ct++) {
        for (int kc = 0; kc < KCHUNK; kc++, g++) {
            CP_WAIT2();
            __syncthreads();
            issue_load(g + 3);

            uint32_t stg = sbase + (uint32_t)(g & (NST - 1)) * STAGE_B;
#pragma unroll
            for (int ks = 0; ks < 2; ks++) {
                uint32_t areg[4][4], breg[8][2];
#pragma unroll
                for (int i = 0; i < 4; i++)
                    LDSM_X4(areg[i][0], areg[i][1], areg[i][2], areg[i][3],
                            stg + aOff + i * (16 * PADK * 2) + ks * 32);
#pragma unroll
                for (int j = 0; j < 8; j++)
                    LDSM_X2(breg[j][0], breg[j][1],
                            stg + bOff + j * (8 * PADK * 2) + ks * 32);
#pragma unroll
                for (int i = 0; i < 4; i++)
#pragma unroll
                    for (int j = 0; j < 8; j++)
                        MMA16816(acc[i][j], areg[i], breg[j]);
            }
        }

        // -------- epilogue: running TOP-2 over this 256-code tile ---------
        int colq = (lane & 3) * 2;
#pragma unroll
        for (int j = 0; j < 8; j++) {
            int col = ct * 256 + warp_n * 64 + j * 8 + colq;
            float2 cn = *(const float2*)&g_cnorm[col];
#pragma unroll
            for (int i = 0; i < 4; i++) {
#pragma unroll
                for (int h = 0; h < 2; h++) {
                    int r = i * 2 + h;
                    float s0 = acc[i][j][h * 2 + 0] - cn.x;
                    float s1 = acc[i][j][h * 2 + 1] - cn.y;
                    if (s0 > b1[r]) { b2[r] = b1[r]; i2[r] = i1[r]; b1[r] = s0; i1[r] = col; }
                    else if (s0 > b2[r]) { b2[r] = s0; i2[r] = col; }
                    if (s1 > b1[r]) { b2[r] = b1[r]; i2[r] = i1[r]; b1[r] = s1; i1[r] = col + 1; }
                    else if (s1 > b2[r]) { b2[r] = s1; i2[r] = col + 1; }
                    acc[i][j][h * 2 + 0] = 0.f;
                    acc[i][j][h * 2 + 1] = 0.f;
                }
            }
        }
    }

    // -------- reduce top-2 across the 4 col-lanes, then across N-warps ----
#pragma unroll
    for (int r = 0; r < 8; r++) {
        float a1 = b1[r], a2 = b2[r];
        int   x1 = i1[r], x2 = i2[r];
#pragma unroll
        for (int off = 1; off <= 2; off <<= 1) {
            float o1 = __shfl_xor_sync(0xffffffffu, a1, off);
            int   y1 = __shfl_xor_sync(0xffffffffu, x1, off);
            float o2 = __shfl_xor_sync(0xffffffffu, a2, off);
            int   y2 = __shfl_xor_sync(0xffffffffu, x2, off);
            if (o1 > a1 || (o1 == a1 && y1 < x1)) {
                // other's best wins; new second = max(a1, o2)
                if (a1 > o2 || (a1 == o2 && x1 < y2)) { a2 = a1; x2 = x1; }
                else { a2 = o2; x2 = y2; }
                a1 = o1; x1 = y1;
            } else {
                if (o1 > a2 || (o1 == a2 && y1 < x2)) { a2 = o1; x2 = y1; }
            }
        }
        if ((lane & 3) == 0) {
            int i = r >> 1, h = r & 1;
            int row = warp_m * 64 + i * 16 + h * 8 + (lane >> 2);
            sB1[row * 4 + warp_n] = a1; sI1[row * 4 + warp_n] = x1;
            sB2[row * 4 + warp_n] = a2; sI2[row * 4 + warp_n] = x2;
        }
    }
    __syncthreads();
    if (tid < 128) {
        float a1 = sB1[tid * 4], a2 = sB2[tid * 4];
        int   x1 = sI1[tid * 4], x2 = sI2[tid * 4];
#pragma unroll
        for (int w = 1; w < 4; w++) {
            float o1 = sB1[tid * 4 + w], o2 = sB2[tid * 4 + w];
            int   y1 = sI1[tid * 4 + w], y2 = sI2[tid * 4 + w];
            if (o1 > a1 || (o1 == a1 && y1 < x1)) {
                if (a1 > o2 || (a1 == o2 && x1 < y2)) { a2 = a1; x2 = x1; }
                else { a2 = o2; x2 = y2; }
                a1 = o1; x1 = y1;
            } else {
                if (o1 > a2 || (o1 == a2 && y1 < x2)) { a2 = o1; x2 = y1; }
            }
        }
        int gr = rowBase + tid;
        g_c1[gr] = x1;
        g_c2[gr] = x2;
    }
}

// ---------------------------------------------------------------------------
// Rescore + gather (fused): one warp per row.  Exact fp32 scores of the two
// candidates decide the winner; then write straight-through output, token,
// histogram count, and loss partial.
// ---------------------------------------------------------------------------
__global__ void vq_rescore(const float* __restrict__ X, const float* __restrict__ C,
                           float* __restrict__ outQ, float* __restrict__ outTok) {
    int w = threadIdx.x >> 5, lane = threadIdx.x & 31;
    int row = blockIdx.x * 8 + w;
    int c1 = g_c1[row], c2 = g_c2[row];

    const float4* xp  = (const float4*)(X + (size_t)row * D_DIM);
    const float4* cp1 = (const float4*)(C + (size_t)c1 * D_DIM);
    const float4* cp2 = (const float4*)(C + (size_t)c2 * D_DIM);
    float4 xa = xp[lane * 2],  xb = xp[lane * 2 + 1];
    float4 qa1 = cp1[lane * 2], qb1 = cp1[lane * 2 + 1];
    float4 qa2 = cp2[lane * 2], qb2 = cp2[lane * 2 + 1];

    float d1 = xa.x * qa1.x + xa.y * qa1.y + xa.z * qa1.z + xa.w * qa1.w
             + xb.x * qb1.x + xb.y * qb1.y + xb.z * qb1.z + xb.w * qb1.w;
    float d2 = xa.x * qa2.x + xa.y * qa2.y + xa.z * qa2.z + xa.w * qa2.w
             + xb.x * qb2.x + xb.y * qb2.y + xb.z * qb2.z + xb.w * qb2.w;
    d1 = warpReduceSum(d1);
    d2 = warpReduceSum(d2);
    float s1 = d1 - g_cnorm[c1];
    float s2 = d2 - g_cnorm[c2];

    bool use2 = (s2 > s1) || (s2 == s1 && c2 < c1);
    int idx = use2 ? c2 : c1;
    float4 qa = use2 ? qa2 : qa1;
    float4 qb = use2 ? qb2 : qb1;

    // straight-through output: x + (q - x), matching reference rounding
    float dax = qa.x - xa.x, day = qa.y - xa.y, daz = qa.z - xa.z, daw = qa.w - xa.w;
    float dbx = qb.x - xb.x, dby = qb.y - xb.y, dbz = qb.z - xb.z, dbw = qb.w - xb.w;
    float4* op = (float4*)(outQ + (size_t)row * D_DIM);
    op[lane * 2]     = make_float4(xa.x + dax, xa.y + day, xa.z + daz, xa.w + daw);
    op[lane * 2 + 1] = make_float4(xb.x + dbx, xb.y + dby, xb.z + dbz, xb.w + dbw);

    if (lane == 0) {
        outTok[row] = (float)idx;
        atomicAdd(&g_counts[idx], 1);
    }

    float s = dax * dax + day * day + daz * daz + daw * daw
            + dbx * dbx + dby * dby + dbz * dbz + dbw * dbw;
    s = warpReduceSum(s);
    __shared__ float ps[8];
    if (lane == 0) ps[w] = s;
    __syncthreads();
    if (w == 0) {
        float v = (lane < 8) ? ps[lane] : 0.f;
        v = warpReduceSum(v);
        if (lane == 0) atomicAdd(&g_loss, (double)v);
    }
}

// ---------------------------------------------------------------------------
// Finalize: losses + perplexity
// ---------------------------------------------------------------------------
__global__ void vq_fin(float* __restrict__ outScal) {
    double ent = 0.0;
    float invN = 1.0f / (float)N_ROWS;
    for (int k = threadIdx.x; k < K_CODES; k += 256) {
        float p = (float)g_counts[k] * invN;
        ent += (double)(p * logf(p + 1e-10f));
    }
    __shared__ double ds[256];
    ds[threadIdx.x] = ent;
    __syncthreads();
    for (int s = 128; s > 0; s >>= 1) {
        if (threadIdx.x < s) ds[threadIdx.x] += ds[threadIdx.x + s];
        __syncthreads();
    }
    if (threadIdx.x == 0) {
        float perp = expf(-(float)ds[0]);
        double l = g_loss / ((double)N_ROWS * (double)D_DIM);
        float lf = (float)l;
        outScal[0] = 1.25f * lf;   // vq_loss
        outScal[1] = 0.25f * lf;   // commitment_loss
        outScal[2] = lf;           // codebook_loss
        outScal[3] = perp;         // perplexity
    }
}

// ---------------------------------------------------------------------------
extern "C" void kernel_launch(void* const* d_in, const int* in_sizes, int n_in,
                              void* d_out, int out_size) {
    const float* X = (const float*)d_in[0];   // [32,1024,256] f32
    const float* C = (const float*)d_in[1];   // [8192,256]    f32
    float* out = (float*)d_out;

    float* outTok  = out + (size_t)N_ROWS * D_DIM;
    float* outScal = outTok + N_ROWS;

    cudaFuncSetAttribute(vq_main, cudaFuncAttributeMaxDynamicSharedMemorySize, SMEM_TOTAL);

    vq_prep_b<<<K_CODES / 8, 256>>>(C);
    vq_prep_a<<<N_ROWS / 8, 256>>>(X);
    vq_main<<<N_ROWS / 128, 256, SMEM_TOTAL>>>();
    vq_rescore<<<N_ROWS / 8, 256>>>(X, C, out, outTok);
    vq_fin<<<1, 256>>>(outScal);
}

// round 12
// speedup vs baseline: 5.4207x; 1.0350x over previous
#include <cuda_runtime.h>
#include <cuda_fp16.h>
#include <math.h>
#include <stdint.h>

// Problem sizes (fixed for this dataset)
#define N_ROWS  32768
#define K_CODES 8192
#define D_DIM   256

// smem staging (K-chunks of 32 fp16)
#define PADK    40           // fp16 elems per smem row (32 data + 8 pad) = 80B
#define A_ST    (128 * PADK * 2)      // 10240 B
#define B_ST    (256 * PADK * 2)      // 20480 B
#define STAGE_B (A_ST + B_ST)         // 30720 B
#define NST     4
#define SMEM_STAGES (NST * STAGE_B)   // 122880
#define SMEM_RED    (128 * 4 * 16)    // top-2 reduce: 4 fields x 4B  = 8192
#define SMEM_TOTAL  (SMEM_STAGES + SMEM_RED)

// -------- scratch (no allocations allowed) --------
__device__ int    g_c1[N_ROWS];                 // approx best candidate
__device__ int    g_c2[N_ROWS];                 // approx runner-up
__device__ int    g_counts[K_CODES];
__device__ float  g_cnorm[K_CODES];             // 0.5*||c||^2 (fp32)
__device__ double g_loss;
__device__ __half g_Ah[(size_t)N_ROWS * D_DIM]; // 16.8 MB (x rounded to fp16)
__device__ __half g_Bh[(size_t)K_CODES * D_DIM];// 4.2 MB  (c rounded to fp16)

// ======================= helpers =======================
__device__ __forceinline__ uint32_t smem_to_u32(const void* p) {
    uint32_t a;
    asm("{ .reg .u64 t; cvta.to.shared.u64 t, %1; cvt.u32.u64 %0, t; }" : "=r"(a) : "l"(p));
    return a;
}
__device__ __forceinline__ float warpReduceSum(float v) {
#pragma unroll
    for (int o = 16; o > 0; o >>= 1) v += __shfl_xor_sync(0xffffffffu, v, o);
    return v;
}

#define CP_ASYNC16(smem_u32, gptr) \
    asm volatile("cp.async.cg.shared.global [%0], [%1], 16;" :: "r"(smem_u32), "l"(gptr) : "memory")
#define CP_COMMIT() asm volatile("cp.async.commit_group;" ::: "memory")
#define CP_WAIT2()  asm volatile("cp.async.wait_group 2;" ::: "memory")

#define LDSM_X4(r0, r1, r2, r3, addr) \
    asm volatile("ldmatrix.sync.aligned.m8n8.x4.shared.b16 {%0,%1,%2,%3}, [%4];" \
        : "=r"(r0), "=r"(r1), "=r"(r2), "=r"(r3) : "r"(addr))
#define LDSM_X2(r0, r1, addr) \
    asm volatile("ldmatrix.sync.aligned.m8n8.x2.shared.b16 {%0,%1}, [%2];" \
        : "=r"(r0), "=r"(r1) : "r"(addr))

#define MMA16816(d, a, b) \
    asm volatile("mma.sync.aligned.m16n8k16.row.col.f32.f16.f16.f32 " \
        "{%0,%1,%2,%3},{%4,%5,%6,%7},{%8,%9},{%0,%1,%2,%3};" \
        : "+f"((d)[0]), "+f"((d)[1]), "+f"((d)[2]), "+f"((d)[3]) \
        : "r"((a)[0]), "r"((a)[1]), "r"((a)[2]), "r"((a)[3]), "r"((b)[0]), "r"((b)[1]))

// Fresh-write variant: D = A*B + 0  (kills per-tile acc zeroing)
#define MMA16816_INIT(d, a, b) \
    asm volatile("mma.sync.aligned.m16n8k16.row.col.f32.f16.f16.f32 " \
        "{%0,%1,%2,%3},{%4,%5,%6,%7},{%8,%9},{%10,%10,%10,%10};" \
        : "=f"((d)[0]), "=f"((d)[1]), "=f"((d)[2]), "=f"((d)[3]) \
        : "r"((a)[0]), "r"((a)[1]), "r"((a)[2]), "r"((a)[3]), "r"((b)[0]), "r"((b)[1]), \
          "f"(0.0f))

// ---------------------------------------------------------------------------
// Prep A: round inputs to fp16 (approx operand).  One warp per row.
// ---------------------------------------------------------------------------
__global__ void vq_prep_a(const float* __restrict__ X) {
    int w = threadIdx.x >> 5, lane = threadIdx.x & 31;
    int row = blockIdx.x * 8 + w;
    const float* x = X + (size_t)row * D_DIM;
    __half* a = g_Ah + (size_t)row * D_DIM;
#pragma unroll
    for (int i = 0; i < 8; i++) {
        int c = lane + 32 * i;
        a[c] = __float2half_rn(x[c]);
    }
}

// ---------------------------------------------------------------------------
// Prep B: fp16 codebook + fp32 half-norms; zero counts/loss (replay-safe).
// ---------------------------------------------------------------------------
__global__ void vq_prep_b(const float* __restrict__ C) {
    int w = threadIdx.x >> 5, lane = threadIdx.x & 31;
    int row = blockIdx.x * 8 + w;
    const float* c = C + (size_t)row * D_DIM;
    __half* b = g_Bh + (size_t)row * D_DIM;
    float s = 0.f;
#pragma unroll
    for (int i = 0; i < 8; i++) {
        int k = lane + 32 * i;
        float v = c[k];
        s += v * v;
        b[k] = __float2half_rn(v);
    }
    s = warpReduceSum(s);
    if (lane == 0) g_cnorm[row] = 0.5f * s;
    if (blockIdx.x < K_CODES / 256) g_counts[blockIdx.x * 256 + threadIdx.x] = 0;
    if (blockIdx.x == 0 && threadIdx.x == 0) g_loss = 0.0;
}

// ---------------------------------------------------------------------------
// Main: fp16 approx GEMM (K=256), CTA = 128 rows x 8192 codes (32 tiles of
// 256), fused per-row TOP-2 tracking.  8 warps 2(M) x 4(N), warp tile 64x64.
// ---------------------------------------------------------------------------
#define NTILES  32            // 8192 / 256
#define KCHUNK  8             // 256 / 32
#define TOTALCH (NTILES * KCHUNK)

__global__ void __launch_bounds__(256, 1) vq_main() {
    extern __shared__ char smem[];
    const uint32_t sbase = smem_to_u32(smem);
    float* sB1 = (float*)(smem + SMEM_STAGES);
    int*   sI1 = (int*)  (smem + SMEM_STAGES + 2048);
    float* sB2 = (float*)(smem + SMEM_STAGES + 4096);
    int*   sI2 = (int*)  (smem + SMEM_STAGES + 6144);

    const int tid  = threadIdx.x;
    const int lane = tid & 31;
    const int wid  = tid >> 5;
    const int warp_m = wid & 1;        // rows warp_m*64
    const int warp_n = wid >> 1;       // cols warp_n*64
    const int rowBase = blockIdx.x * 128;

    float acc[4][8][4];                // freshly written each tile by MMA_INIT

    float b1[8], b2[8];
    int   i1[8], i2[8];
#pragma unroll
    for (int r = 0; r < 8; r++) { b1[r] = b2[r] = -INFINITY; i1[r] = 0; i2[r] = 1; }

    // producer: A 512 x16B ops, B 1024 x16B ops per chunk
    auto issue_load = [&](int g) {
        if (g < TOTALCH) {
            int ct = g / KCHUNK, kc = g % KCHUNK, st = g & (NST - 1);
            uint32_t sa = sbase + st * STAGE_B;
            uint32_t sb = sa + A_ST;
            int kbase = kc * 32;
#pragma unroll
            for (int r = 0; r < 2; r++) {               // A: 128 rows x 64B
                int id = tid + 256 * r;
                int row = id >> 2, seg = id & 3;
                uint32_t so = sa + row * (PADK * 2) + seg * 16;
                const __half* gp = g_Ah + (size_t)(rowBase + row) * D_DIM + kbase + seg * 8;
                CP_ASYNC16(so, gp);
            }
#pragma unroll
            for (int r = 0; r < 4; r++) {               // B: 256 rows x 64B
                int id = tid + 256 * r;
                int row = id >> 2, seg = id & 3;
                uint32_t so = sb + row * (PADK * 2) + seg * 16;
                const __half* gp = g_Bh + (size_t)(ct * 256 + row) * D_DIM + kbase + seg * 8;
                CP_ASYNC16(so, gp);
            }
        }
        CP_COMMIT();
    };

    issue_load(0); issue_load(1); issue_load(2);

    const int l15 = lane & 15;
    const int colq = (lane & 3) * 2;
    const uint32_t aOff = (uint32_t)((warp_m * 64 + (lane & 15)) * (PADK * 2) + ((lane >> 4) * 8) * 2);
    const uint32_t bOff = (uint32_t)(A_ST + (warp_n * 64 + (l15 & 7)) * (PADK * 2) + ((l15 >> 3) * 8) * 2);

    // one k-chunk: wait pipeline, refill, ldmatrix + 64 MMAs
    auto do_chunk = [&](int gg, bool first) {
        CP_WAIT2();
        __syncthreads();
        issue_load(gg + 3);
        uint32_t stg = sbase + (uint32_t)(gg & (NST - 1)) * STAGE_B;
#pragma unroll
        for (int ks = 0; ks < 2; ks++) {
            uint32_t areg[4][4], breg[8][2];
#pragma unroll
            for (int i = 0; i < 4; i++)
                LDSM_X4(areg[i][0], areg[i][1], areg[i][2], areg[i][3],
                        stg + aOff + i * (16 * PADK * 2) + ks * 32);
#pragma unroll
            for (int j = 0; j < 8; j++)
                LDSM_X2(breg[j][0], breg[j][1],
                        stg + bOff + j * (8 * PADK * 2) + ks * 32);
            if (first && ks == 0) {
#pragma unroll
                for (int i = 0; i < 4; i++)
#pragma unroll
                    for (int j = 0; j < 8; j++)
                        MMA16816_INIT(acc[i][j], areg[i], breg[j]);
            } else {
#pragma unroll
                for (int i = 0; i < 4; i++)
#pragma unroll
                    for (int j = 0; j < 8; j++)
                        MMA16816(acc[i][j], areg[i], breg[j]);
            }
        }
    };

    for (int ct = 0; ct < NTILES; ct++) {
        // prefetch this tile's cnorms into regs; latency hidden by 8 MMA chunks
        float cnv[16];
#pragma unroll
        for (int j = 0; j < 8; j++) {
            float2 t = *(const float2*)&g_cnorm[ct * 256 + warp_n * 64 + j * 8 + colq];
            cnv[2 * j] = t.x; cnv[2 * j + 1] = t.y;
        }

        do_chunk(ct * KCHUNK, true);
#pragma unroll 1
        for (int kc = 1; kc < KCHUNK; kc++)
            do_chunk(ct * KCHUNK + kc, false);

        // -------- epilogue: branchless common path, rare exact fixup ------
#pragma unroll
        for (int j = 0; j < 8; j++) {
            int col = ct * 256 + warp_n * 64 + j * 8 + colq;
            float cx = cnv[2 * j], cy = cnv[2 * j + 1];
#pragma unroll
            for (int i = 0; i < 4; i++) {
#pragma unroll
                for (int h = 0; h < 2; h++) {
                    int r = i * 2 + h;
                    float s0 = acc[i][j][h * 2 + 0] - cx;
                    float s1 = acc[i][j][h * 2 + 1] - cy;
                    float m = fmaxf(s0, s1);
                    if (m > b2[r]) {   // rare: ~2 ln(2048) updates/thread total
                        if (s0 > b1[r]) { b2[r] = b1[r]; i2[r] = i1[r]; b1[r] = s0; i1[r] = col; }
                        else if (s0 > b2[r]) { b2[r] = s0; i2[r] = col; }
                        if (s1 > b1[r]) { b2[r] = b1[r]; i2[r] = i1[r]; b1[r] = s1; i1[r] = col + 1; }
                        else if (s1 > b2[r]) { b2[r] = s1; i2[r] = col + 1; }
                    }
                }
            }
        }
    }

    // -------- reduce top-2 across the 4 col-lanes, then across N-warps ----
#pragma unroll
    for (int r = 0; r < 8; r++) {
        float a1 = b1[r], a2 = b2[r];
        int   x1 = i1[r], x2 = i2[r];
#pragma unroll
        for (int off = 1; off <= 2; off <<= 1) {
            float o1 = __shfl_xor_sync(0xffffffffu, a1, off);
            int   y1 = __shfl_xor_sync(0xffffffffu, x1, off);
            float o2 = __shfl_xor_sync(0xffffffffu, a2, off);
            int   y2 = __shfl_xor_sync(0xffffffffu, x2, off);
            if (o1 > a1 || (o1 == a1 && y1 < x1)) {
                if (a1 > o2 || (a1 == o2 && x1 < y2)) { a2 = a1; x2 = x1; }
                else { a2 = o2; x2 = y2; }
                a1 = o1; x1 = y1;
            } else {
                if (o1 > a2 || (o1 == a2 && y1 < x2)) { a2 = o1; x2 = y1; }
            }
        }
        if ((lane & 3) == 0) {
            int i = r >> 1, h = r & 1;
            int row = warp_m * 64 + i * 16 + h * 8 + (lane >> 2);
            sB1[row * 4 + warp_n] = a1; sI1[row * 4 + warp_n] = x1;
            sB2[row * 4 + warp_n] = a2; sI2[row * 4 + warp_n] = x2;
        }
    }
    __syncthreads();
    if (tid < 128) {
        float a1 = sB1[tid * 4], a2 = sB2[tid * 4];
        int   x1 = sI1[tid * 4], x2 = sI2[tid * 4];
#pragma unroll
        for (int w = 1; w < 4; w++) {
            float o1 = sB1[tid * 4 + w], o2 = sB2[tid * 4 + w];
            int   y1 = sI1[tid * 4 + w], y2 = sI2[tid * 4 + w];
            if (o1 > a1 || (o1 == a1 && y1 < x1)) {
                if (a1 > o2 || (a1 == o2 && x1 < y2)) { a2 = a1; x2 = x1; }
                else { a2 = o2; x2 = y2; }
                a1 = o1; x1 = y1;
            } else {
                if (o1 > a2 || (o1 == a2 && y1 < x2)) { a2 = o1; x2 = y1; }
            }
        }
        int gr = rowBase + tid;
        g_c1[gr] = x1;
        g_c2[gr] = x2;
    }
}

// ---------------------------------------------------------------------------
// Rescore + gather (fused): one warp per row.  Exact fp32 scores of the two
// candidates decide the winner; then write straight-through output, token,
// histogram count, and loss partial.
// ---------------------------------------------------------------------------
__global__ void vq_rescore(const float* __restrict__ X, const float* __restrict__ C,
                           float* __restrict__ outQ, float* __restrict__ outTok) {
    int w = threadIdx.x >> 5, lane = threadIdx.x & 31;
    int row = blockIdx.x * 8 + w;
    int c1 = g_c1[row], c2 = g_c2[row];

    const float4* xp  = (const float4*)(X + (size_t)row * D_DIM);
    const float4* cp1 = (const float4*)(C + (size_t)c1 * D_DIM);
    const float4* cp2 = (const float4*)(C + (size_t)c2 * D_DIM);
    float4 xa = xp[lane * 2],  xb = xp[lane * 2 + 1];
    float4 qa1 = cp1[lane * 2], qb1 = cp1[lane * 2 + 1];
    float4 qa2 = cp2[lane * 2], qb2 = cp2[lane * 2 + 1];

    float d1 = xa.x * qa1.x + xa.y * qa1.y + xa.z * qa1.z + xa.w * qa1.w
             + xb.x * qb1.x + xb.y * qb1.y + xb.z * qb1.z + xb.w * qb1.w;
    float d2 = xa.x * qa2.x + xa.y * qa2.y + xa.z * qa2.z + xa.w * qa2.w
             + xb.x * qb2.x + xb.y * qb2.y + xb.z * qb2.z + xb.w * qb2.w;
    d1 = warpReduceSum(d1);
    d2 = warpReduceSum(d2);
    float s1 = d1 - g_cnorm[c1];
    float s2 = d2 - g_cnorm[c2];

    bool use2 = (s2 > s1) || (s2 == s1 && c2 < c1);
    int idx = use2 ? c2 : c1;
    float4 qa = use2 ? qa2 : qa1;
    float4 qb = use2 ? qb2 : qb1;

    // straight-through output: x + (q - x), matching reference rounding
    float dax = qa.x - xa.x, day = qa.y - xa.y, daz = qa.z - xa.z, daw = qa.w - xa.w;
    float dbx = qb.x - xb.x, dby = qb.y - xb.y, dbz = qb.z - xb.z, dbw = qb.w - xb.w;
    float4* op = (float4*)(outQ + (size_t)row * D_DIM);
    op[lane * 2]     = make_float4(xa.x + dax, xa.y + day, xa.z + daz, xa.w + daw);
    op[lane * 2 + 1] = make_float4(xb.x + dbx, xb.y + dby, xb.z + dbz, xb.w + dbw);

    if (lane == 0) {
        outTok[row] = (float)idx;
        atomicAdd(&g_counts[idx], 1);
    }

    float s = dax * dax + day * day + daz * daz + daw * daw
            + dbx * dbx + dby * dby + dbz * dbz + dbw * dbw;
    s = warpReduceSum(s);
    __shared__ float ps[8];
    if (lane == 0) ps[w] = s;
    __syncthreads();
    if (w == 0) {
        float v = (lane < 8) ? ps[lane] : 0.f;
        v = warpReduceSum(v);
        if (lane == 0) atomicAdd(&g_loss, (double)v);
    }
}

// ---------------------------------------------------------------------------
// Finalize: losses + perplexity (1024 threads)
// ---------------------------------------------------------------------------
__global__ void vq_fin(float* __restrict__ outScal) {
    double ent = 0.0;
    float invN = 1.0f / (float)N_ROWS;
    for (int k = threadIdx.x; k < K_CODES; k += 1024) {
        float p = (float)g_counts[k] * invN;
        ent += (double)(p * logf(p + 1e-10f));
    }
    __shared__ double ds[1024];
    ds[threadIdx.x] = ent;
    __syncthreads();
    for (int s = 512; s > 0; s >>= 1) {
        if (threadIdx.x < s) ds[threadIdx.x] += ds[threadIdx.x + s];
        __syncthreads();
    }
    if (threadIdx.x == 0) {
        float perp = expf(-(float)ds[0]);
        double l = g_loss / ((double)N_ROWS * (double)D_DIM);
        float lf = (float)l;
        outScal[0] = 1.25f * lf;   // vq_loss
        outScal[1] = 0.25f * lf;   // commitment_loss
        outScal[2] = lf;           // codebook_loss
        outScal[3] = perp;         // perplexity
    }
}

// ---------------------------------------------------------------------------
extern "C" void kernel_launch(void* const* d_in, const int* in_sizes, int n_in,
                              void* d_out, int out_size) {
    const float* X = (const float*)d_in[0];   // [32,1024,256] f32
    const float* C = (const float*)d_in[1];   // [8192,256]    f32
    float* out = (float*)d_out;

    float* outTok  = out + (size_t)N_ROWS * D_DIM;
    float* outScal = outTok + N_ROWS;

    cudaFuncSetAttribute(vq_main, cudaFuncAttributeMaxDynamicSharedMemorySize, SMEM_TOTAL);

    vq_prep_b<<<K_CODES / 8, 256>>>(C);
    vq_prep_a<<<N_ROWS / 8, 256>>>(X);
    vq_main<<<N_ROWS / 128, 256, SMEM_TOTAL>>>();
    vq_rescore<<<N_ROWS / 8, 256>>>(X, C, out, outTok);
    vq_fin<<<1, 1024>>>(outScal);
}

// round 13
// speedup vs baseline: 5.5327x; 1.0207x over previous
#include <cuda_runtime.h>
#include <cuda_fp16.h>
#include <math.h>
#include <stdint.h>

// Problem sizes (fixed for this dataset)
#define N_ROWS  32768
#define K_CODES 8192
#define D_DIM   256

// Work decomposition: unit = (128-row tile) x (2048-code quarter)
#define NQUART   4
#define QCODES   2048
#define NUNITS   ((N_ROWS / 128) * NQUART)   // 1024
#define NTILE_U  (QCODES / 256)              // 8 tiles of 256 codes per unit
#define KCHUNK   8                           // 256 K / 32
#define CHUNKS_U (NTILE_U * KCHUNK)          // 64

// smem: resident A + 4-stage B pipeline + reduce scratch
#define APAD_B  528                          // A row stride bytes (512 data + 16)
#define A_RES_B (128 * APAD_B)               // 67584
#define PADK    40                           // B smem row: 32 fp16 + 8 pad = 80B
#define B_ST    (256 * PADK * 2)             // 20480
#define NST     4
#define SMEM_B  (NST * B_ST)                 // 81920
#define SMEM_RED 8192
#define SMEM_TOTAL (A_RES_B + SMEM_B + SMEM_RED)   // 157696

// -------- scratch (no allocations allowed) --------
__device__ int    g_c1[NQUART * N_ROWS];        // per-quarter approx best
__device__ int    g_c2[NQUART * N_ROWS];        // per-quarter approx runner-up
__device__ int    g_counts[K_CODES];
__device__ float  g_cnorm[K_CODES];             // 0.5*||c||^2 (fp32)
__device__ double g_loss;
__device__ int    g_unitCtr;
__device__ __half g_Ah[(size_t)N_ROWS * D_DIM]; // 16.8 MB
__device__ __half g_Bh[(size_t)K_CODES * D_DIM];// 4.2 MB

// ======================= helpers =======================
__device__ __forceinline__ uint32_t smem_to_u32(const void* p) {
    uint32_t a;
    asm("{ .reg .u64 t; cvta.to.shared.u64 t, %1; cvt.u32.u64 %0, t; }" : "=r"(a) : "l"(p));
    return a;
}
__device__ __forceinline__ float warpReduceSum(float v) {
#pragma unroll
    for (int o = 16; o > 0; o >>= 1) v += __shfl_xor_sync(0xffffffffu, v, o);
    return v;
}

#define CP_ASYNC16(smem_u32, gptr) \
    asm volatile("cp.async.cg.shared.global [%0], [%1], 16;" :: "r"(smem_u32), "l"(gptr) : "memory")
#define CP_COMMIT()  asm volatile("cp.async.commit_group;" ::: "memory")
#define CP_WAIT2()   asm volatile("cp.async.wait_group 2;" ::: "memory")
#define CP_WAITALL() asm volatile("cp.async.wait_all;" ::: "memory")

#define LDSM_X4(r0, r1, r2, r3, addr) \
    asm volatile("ldmatrix.sync.aligned.m8n8.x4.shared.b16 {%0,%1,%2,%3}, [%4];" \
        : "=r"(r0), "=r"(r1), "=r"(r2), "=r"(r3) : "r"(addr))
#define LDSM_X2(r0, r1, addr) \
    asm volatile("ldmatrix.sync.aligned.m8n8.x2.shared.b16 {%0,%1}, [%2];" \
        : "=r"(r0), "=r"(r1) : "r"(addr))

#define MMA16816(d, a, b) \
    asm volatile("mma.sync.aligned.m16n8k16.row.col.f32.f16.f16.f32 " \
        "{%0,%1,%2,%3},{%4,%5,%6,%7},{%8,%9},{%0,%1,%2,%3};" \
        : "+f"((d)[0]), "+f"((d)[1]), "+f"((d)[2]), "+f"((d)[3]) \
        : "r"((a)[0]), "r"((a)[1]), "r"((a)[2]), "r"((a)[3]), "r"((b)[0]), "r"((b)[1]))

#define MMA16816_INIT(d, a, b) \
    asm volatile("mma.sync.aligned.m16n8k16.row.col.f32.f16.f16.f32 " \
        "{%0,%1,%2,%3},{%4,%5,%6,%7},{%8,%9},{%10,%10,%10,%10};" \
        : "=f"((d)[0]), "=f"((d)[1]), "=f"((d)[2]), "=f"((d)[3]) \
        : "r"((a)[0]), "r"((a)[1]), "r"((a)[2]), "r"((a)[3]), "r"((b)[0]), "r"((b)[1]), \
          "f"(0.0f))

// ---------------------------------------------------------------------------
// Prep A: round inputs to fp16.  One warp per row.
// ---------------------------------------------------------------------------
__global__ void vq_prep_a(const float* __restrict__ X) {
    int w = threadIdx.x >> 5, lane = threadIdx.x & 31;
    int row = blockIdx.x * 8 + w;
    const float* x = X + (size_t)row * D_DIM;
    __half* a = g_Ah + (size_t)row * D_DIM;
#pragma unroll
    for (int i = 0; i < 8; i++) {
        int c = lane + 32 * i;
        a[c] = __float2half_rn(x[c]);
    }
}

// ---------------------------------------------------------------------------
// Prep B: fp16 codebook + fp32 half-norms; zero counters (replay-safe).
// ---------------------------------------------------------------------------
__global__ void vq_prep_b(const float* __restrict__ C) {
    int w = threadIdx.x >> 5, lane = threadIdx.x & 31;
    int row = blockIdx.x * 8 + w;
    const float* c = C + (size_t)row * D_DIM;
    __half* b = g_Bh + (size_t)row * D_DIM;
    float s = 0.f;
#pragma unroll
    for (int i = 0; i < 8; i++) {
        int k = lane + 32 * i;
        float v = c[k];
        s += v * v;
        b[k] = __float2half_rn(v);
    }
    s = warpReduceSum(s);
    if (lane == 0) g_cnorm[row] = 0.5f * s;
    if (blockIdx.x < K_CODES / 256) g_counts[blockIdx.x * 256 + threadIdx.x] = 0;
    if (blockIdx.x == 0 && threadIdx.x == 0) { g_loss = 0.0; g_unitCtr = 0; }
}

// ---------------------------------------------------------------------------
// Main: persistent CTAs pull (rowTile, quarter) units from a queue.
// Per unit: A (128x256 fp16) resident in smem; B streamed through a 4-stage
// cp.async pipeline; fp16 HMMA; per-row top-2 over the 2048-code quarter.
// 8 warps in 2(M) x 4(N); warp tile 64x64.
// ---------------------------------------------------------------------------
__global__ void __launch_bounds__(256, 1) vq_main() {
    extern __shared__ char smem[];
    const uint32_t sbase = smem_to_u32(smem);
    float* sB1 = (float*)(smem + A_RES_B + SMEM_B);
    int*   sI1 = (int*)  (smem + A_RES_B + SMEM_B + 2048);
    float* sB2 = (float*)(smem + A_RES_B + SMEM_B + 4096);
    int*   sI2 = (int*)  (smem + A_RES_B + SMEM_B + 6144);
    __shared__ int sU;

    const int tid  = threadIdx.x;
    const int lane = tid & 31;
    const int wid  = tid >> 5;
    const int warp_m = wid & 1;
    const int warp_n = wid >> 1;
    const int l15  = lane & 15;
    const int colq = (lane & 3) * 2;

    const uint32_t aOff = (uint32_t)((warp_m * 64 + (lane & 15)) * APAD_B + ((lane >> 4) * 8) * 2);
    const uint32_t bRel = (uint32_t)(A_RES_B + (warp_n * 64 + (l15 & 7)) * (PADK * 2) + ((l15 >> 3) * 8) * 2);

    while (true) {
        CP_WAITALL();
        __syncthreads();                       // smem (A region, stages, reduce) reusable
        if (tid == 0) sU = atomicAdd(&g_unitCtr, 1);
        __syncthreads();
        const int u = sU;
        if (u >= NUNITS) break;
        const int rowBase  = (u >> 2) * 128;
        const int q        = u & 3;
        const int codeBase = q * QCODES;

        // ---- load resident A: 128 rows x 512B, 16 cp.async per thread ----
#pragma unroll
        for (int r = 0; r < 16; r++) {
            int i = tid + 256 * r;             // 0..4095
            int row = i >> 5, seg = i & 31;
            CP_ASYNC16(sbase + row * APAD_B + seg * 16,
                       g_Ah + (size_t)(rowBase + row) * D_DIM + seg * 8);
        }
        CP_COMMIT();

        // ---- B producer: 4 cp.async per thread per 32-K chunk ----
        auto issue_load = [&](int g) {
            if (g < CHUNKS_U) {
                int ct = g >> 3, kc = g & 7, st = g & (NST - 1);
                uint32_t sb = sbase + A_RES_B + st * B_ST;
                int kbase = kc * 32;
#pragma unroll
                for (int r = 0; r < 4; r++) {
                    int id = tid + 256 * r;    // 0..1023
                    int row = id >> 2, seg = id & 3;
                    uint32_t so = sb + row * (PADK * 2) + seg * 16;
                    const __half* gp = g_Bh + (size_t)(codeBase + ct * 256 + row) * D_DIM + kbase + seg * 8;
                    CP_ASYNC16(so, gp);
                }
            }
            CP_COMMIT();
        };

        issue_load(0); issue_load(1); issue_load(2);

        float b1[8], b2[8];
        int   i1[8], i2[8];
#pragma unroll
        for (int r = 0; r < 8; r++) { b1[r] = b2[r] = -INFINITY; i1[r] = 0; i2[r] = 1; }

        float acc[4][8][4];

        auto do_chunk = [&](int gg, int kc, bool first) {
            CP_WAIT2();
            __syncthreads();
            issue_load(gg + 3);
            uint32_t stg = sbase + A_RES_B + (uint32_t)(gg & (NST - 1)) * B_ST;
            uint32_t aCk = sbase + aOff + kc * 64;
#pragma unroll
            for (int ks = 0; ks < 2; ks++) {
                uint32_t areg[4][4], breg[8][2];
#pragma unroll
                for (int i = 0; i < 4; i++)
                    LDSM_X4(areg[i][0], areg[i][1], areg[i][2], areg[i][3],
                            aCk + i * (16 * APAD_B) + ks * 32);
#pragma unroll
                for (int j = 0; j < 8; j++)
                    LDSM_X2(breg[j][0], breg[j][1],
                            stg + (bRel - A_RES_B) + j * (8 * PADK * 2) + ks * 32);
                if (first && ks == 0) {
#pragma unroll
                    for (int i = 0; i < 4; i++)
#pragma unroll
                        for (int j = 0; j < 8; j++)
                            MMA16816_INIT(acc[i][j], areg[i], breg[j]);
                } else {
#pragma unroll
                    for (int i = 0; i < 4; i++)
#pragma unroll
                        for (int j = 0; j < 8; j++)
                            MMA16816(acc[i][j], areg[i], breg[j]);
                }
            }
        };

        for (int ct = 0; ct < NTILE_U; ct++) {
            float cnv[16];
#pragma unroll
            for (int j = 0; j < 8; j++) {
                float2 t = *(const float2*)&g_cnorm[codeBase + ct * 256 + warp_n * 64 + j * 8 + colq];
                cnv[2 * j] = t.x; cnv[2 * j + 1] = t.y;
            }

            do_chunk(ct * KCHUNK, 0, true);
#pragma unroll 1
            for (int kc = 1; kc < KCHUNK; kc++)
                do_chunk(ct * KCHUNK + kc, kc, false);

            // epilogue: branchless common path, rare exact fixup
#pragma unroll
            for (int j = 0; j < 8; j++) {
                int col = codeBase + ct * 256 + warp_n * 64 + j * 8 + colq;
                float cx = cnv[2 * j], cy = cnv[2 * j + 1];
#pragma unroll
                for (int i = 0; i < 4; i++) {
#pragma unroll
                    for (int h = 0; h < 2; h++) {
                        int r = i * 2 + h;
                        float s0 = acc[i][j][h * 2 + 0] - cx;
                        float s1 = acc[i][j][h * 2 + 1] - cy;
                        float m = fmaxf(s0, s1);
                        if (m > b2[r]) {
                            if (s0 > b1[r]) { b2[r] = b1[r]; i2[r] = i1[r]; b1[r] = s0; i1[r] = col; }
                            else if (s0 > b2[r]) { b2[r] = s0; i2[r] = col; }
                            if (s1 > b1[r]) { b2[r] = b1[r]; i2[r] = i1[r]; b1[r] = s1; i1[r] = col + 1; }
                            else if (s1 > b2[r]) { b2[r] = s1; i2[r] = col + 1; }
                        }
                    }
                }
            }
        }

        // ---- unit-end reduce: 4 col-lanes, then across N-warps ----
#pragma unroll
        for (int r = 0; r < 8; r++) {
            float a1 = b1[r], a2 = b2[r];
            int   x1 = i1[r], x2 = i2[r];
#pragma unroll
            for (int off = 1; off <= 2; off <<= 1) {
                float o1 = __shfl_xor_sync(0xffffffffu, a1, off);
                int   y1 = __shfl_xor_sync(0xffffffffu, x1, off);
                float o2 = __shfl_xor_sync(0xffffffffu, a2, off);
                int   y2 = __shfl_xor_sync(0xffffffffu, x2, off);
                if (o1 > a1 || (o1 == a1 && y1 < x1)) {
                    if (a1 > o2 || (a1 == o2 && x1 < y2)) { a2 = a1; x2 = x1; }
                    else { a2 = o2; x2 = y2; }
                    a1 = o1; x1 = y1;
                } else {
                    if (o1 > a2 || (o1 == a2 && y1 < x2)) { a2 = o1; x2 = y1; }
                }
            }
            if ((lane & 3) == 0) {
                int i = r >> 1, h = r & 1;
                int row = warp_m * 64 + i * 16 + h * 8 + (lane >> 2);
                sB1[row * 4 + warp_n] = a1; sI1[row * 4 + warp_n] = x1;
                sB2[row * 4 + warp_n] = a2; sI2[row * 4 + warp_n] = x2;
            }
        }
        __syncthreads();
        if (tid < 128) {
            float a1 = sB1[tid * 4], a2 = sB2[tid * 4];
            int   x1 = sI1[tid * 4], x2 = sI2[tid * 4];
#pragma unroll
            for (int w = 1; w < 4; w++) {
                float o1 = sB1[tid * 4 + w], o2 = sB2[tid * 4 + w];
                int   y1 = sI1[tid * 4 + w], y2 = sI2[tid * 4 + w];
                if (o1 > a1 || (o1 == a1 && y1 < x1)) {
                    if (a1 > o2 || (a1 == o2 && x1 < y2)) { a2 = a1; x2 = x1; }
                    else { a2 = o2; x2 = y2; }
                    a1 = o1; x1 = y1;
                } else {
                    if (o1 > a2 || (o1 == a2 && y1 < x2)) { a2 = o1; x2 = y1; }
                }
            }
            int gr = rowBase + tid;
            g_c1[q * N_ROWS + gr] = x1;
            g_c2[q * N_ROWS + gr] = x2;
        }
    }
}

// ---------------------------------------------------------------------------
// Rescore + gather: one warp per row.  Exact fp32 scores of the 8 candidates
// (top-2 from each quarter) decide; then ST output, token, count, loss.
// ---------------------------------------------------------------------------
__global__ void vq_rescore(const float* __restrict__ X, const float* __restrict__ C,
                           float* __restrict__ outQ, float* __restrict__ outTok) {
    int w = threadIdx.x >> 5, lane = threadIdx.x & 31;
    int row = blockIdx.x * 8 + w;

    int cand[8];
#pragma unroll
    for (int q = 0; q < 4; q++) {
        cand[2 * q]     = g_c1[q * N_ROWS + row];
        cand[2 * q + 1] = g_c2[q * N_ROWS + row];
    }

    const float4* xp = (const float4*)(X + (size_t)row * D_DIM);
    float4 xa = xp[lane * 2], xb = xp[lane * 2 + 1];

    float best = -INFINITY;
    int   bi   = K_CODES;
#pragma unroll
    for (int c = 0; c < 8; c++) {
        const float4* cp = (const float4*)(C + (size_t)cand[c] * D_DIM);
        float4 qa = cp[lane * 2], qb = cp[lane * 2 + 1];
        float d = xa.x * qa.x + xa.y * qa.y + xa.z * qa.z + xa.w * qa.w
                + xb.x * qb.x + xb.y * qb.y + xb.z * qb.z + xb.w * qb.w;
        d = warpReduceSum(d);
        float s = d - g_cnorm[cand[c]];
        if (s > best || (s == best && cand[c] < bi)) { best = s; bi = cand[c]; }
    }

    // gather winner row, write straight-through output
    const float4* cw = (const float4*)(C + (size_t)bi * D_DIM);
    float4 qa = cw[lane * 2], qb = cw[lane * 2 + 1];
    float dax = qa.x - xa.x, day = qa.y - xa.y, daz = qa.z - xa.z, daw = qa.w - xa.w;
    float dbx = qb.x - xb.x, dby = qb.y - xb.y, dbz = qb.z - xb.z, dbw = qb.w - xb.w;
    float4* op = (float4*)(outQ + (size_t)row * D_DIM);
    op[lane * 2]     = make_float4(xa.x + dax, xa.y + day, xa.z + daz, xa.w + daw);
    op[lane * 2 + 1] = make_float4(xb.x + dbx, xb.y + dby, xb.z + dbz, xb.w + dbw);

    if (lane == 0) {
        outTok[row] = (float)bi;
        atomicAdd(&g_counts[bi], 1);
    }

    float s = dax * dax + day * day + daz * daz + daw * daw
            + dbx * dbx + dby * dby + dbz * dbz + dbw * dbw;
    s = warpReduceSum(s);
    __shared__ float ps[8];
    if (lane == 0) ps[w] = s;
    __syncthreads();
    if (w == 0) {
        float v = (lane < 8) ? ps[lane] : 0.f;
        v = warpReduceSum(v);
        if (lane == 0) atomicAdd(&g_loss, (double)v);
    }
}

// ---------------------------------------------------------------------------
// Finalize: losses + perplexity (1024 threads)
// ---------------------------------------------------------------------------
__global__ void vq_fin(float* __restrict__ outScal) {
    double ent = 0.0;
    float invN = 1.0f / (float)N_ROWS;
    for (int k = threadIdx.x; k < K_CODES; k += 1024) {
        float p = (float)g_counts[k] * invN;
        ent += (double)(p * logf(p + 1e-10f));
    }
    __shared__ double ds[1024];
    ds[threadIdx.x] = ent;
    __syncthreads();
    for (int s = 512; s > 0; s >>= 1) {
        if (threadIdx.x < s) ds[threadIdx.x] += ds[threadIdx.x + s];
        __syncthreads();
    }
    if (threadIdx.x == 0) {
        float perp = expf(-(float)ds[0]);
        double l = g_loss / ((double)N_ROWS * (double)D_DIM);
        float lf = (float)l;
        outScal[0] = 1.25f * lf;   // vq_loss
        outScal[1] = 0.25f * lf;   // commitment_loss
        outScal[2] = lf;           // codebook_loss
        outScal[3] = perp;         // perplexity
    }
}

// ---------------------------------------------------------------------------
extern "C" void kernel_launch(void* const* d_in, const int* in_sizes, int n_in,
                              void* d_out, int out_size) {
    const float* X = (const float*)d_in[0];   // [32,1024,256] f32
    const float* C = (const float*)d_in[1];   // [8192,256]    f32
    float* out = (float*)d_out;

    float* outTok  = out + (size_t)N_ROWS * D_DIM;
    float* outScal = outTok + N_ROWS;

    cudaFuncSetAttribute(vq_main, cudaFuncAttributeMaxDynamicSharedMemorySize, SMEM_TOTAL);

    vq_prep_b<<<K_CODES / 8, 256>>>(C);
    vq_prep_a<<<N_ROWS / 8, 256>>>(X);
    vq_main<<<152, 256, SMEM_TOTAL>>>();      // persistent, work-queue
    vq_rescore<<<N_ROWS / 8, 256>>>(X, C, out, outTok);
    vq_fin<<<1, 1024>>>(outScal);
}

// round 14
// speedup vs baseline: 6.8710x; 1.2419x over previous
#include <cuda_runtime.h>
#include <cuda_fp16.h>
#include <math.h>
#include <stdint.h>

// Problem sizes (fixed for this dataset)
#define N_ROWS  32768
#define K_CODES 8192
#define D_DIM   256

// Work decomposition: unit = (64-row tile) x (1024-code eighth)
#define NEIGHTH  8
#define ECODES   1024
#define NUNITS   ((N_ROWS / 64) * NEIGHTH)   // 4096
#define NTILE_U  (ECODES / 128)              // 8 col-tiles of 128 per unit
#define KCHUNK   8                           // 256 K / 32
#define CHUNKS_U (NTILE_U * KCHUNK)          // 64

// smem: resident A (64 rows) + 3-stage B pipeline + reduce scratch
#define APAD_B  528                          // A row stride bytes (512 data + 16)
#define A_RES_B (64 * APAD_B)                // 33792
#define PADK    40                           // B smem row: 32 fp16 + 8 pad = 80B
#define B_ST    (128 * PADK * 2)             // 10240
#define NST     3
#define SMEM_B  (NST * B_ST)                 // 30720
#define SMEM_RED 4096                        // 64 rows x 4 warps x 4 fields x 4B
#define SMEM_TOTAL (A_RES_B + SMEM_B + SMEM_RED)   // 68608

#define TAU 0.08f                            // rescore margin (fp16 noise ~6e-3)

// -------- scratch (no allocations allowed) --------
__device__ int    g_c1[NEIGHTH * N_ROWS];
__device__ int    g_c2[NEIGHTH * N_ROWS];
__device__ float  g_s1[NEIGHTH * N_ROWS];
__device__ float  g_s2[NEIGHTH * N_ROWS];
__device__ int    g_counts[K_CODES];
__device__ float  g_cnorm[K_CODES];             // 0.5*||c||^2 (fp32)
__device__ double g_loss;
__device__ int    g_unitCtr;
__device__ __half g_Ah[(size_t)N_ROWS * D_DIM]; // 16.8 MB
__device__ __half g_Bh[(size_t)K_CODES * D_DIM];// 4.2 MB

// ======================= helpers =======================
__device__ __forceinline__ uint32_t smem_to_u32(const void* p) {
    uint32_t a;
    asm("{ .reg .u64 t; cvta.to.shared.u64 t, %1; cvt.u32.u64 %0, t; }" : "=r"(a) : "l"(p));
    return a;
}
__device__ __forceinline__ float warpReduceSum(float v) {
#pragma unroll
    for (int o = 16; o > 0; o >>= 1) v += __shfl_xor_sync(0xffffffffu, v, o);
    return v;
}

#define CP_ASYNC16(smem_u32, gptr) \
    asm volatile("cp.async.cg.shared.global [%0], [%1], 16;" :: "r"(smem_u32), "l"(gptr) : "memory")
#define CP_COMMIT()  asm volatile("cp.async.commit_group;" ::: "memory")
#define CP_WAIT1()   asm volatile("cp.async.wait_group 1;" ::: "memory")
#define CP_WAITALL() asm volatile("cp.async.wait_all;" ::: "memory")

#define LDSM_X4(r0, r1, r2, r3, addr) \
    asm volatile("ldmatrix.sync.aligned.m8n8.x4.shared.b16 {%0,%1,%2,%3}, [%4];" \
        : "=r"(r0), "=r"(r1), "=r"(r2), "=r"(r3) : "r"(addr))
#define LDSM_X2(r0, r1, addr) \
    asm volatile("ldmatrix.sync.aligned.m8n8.x2.shared.b16 {%0,%1}, [%2];" \
        : "=r"(r0), "=r"(r1) : "r"(addr))

#define MMA16816(d, a, b) \
    asm volatile("mma.sync.aligned.m16n8k16.row.col.f32.f16.f16.f32 " \
        "{%0,%1,%2,%3},{%4,%5,%6,%7},{%8,%9},{%0,%1,%2,%3};" \
        : "+f"((d)[0]), "+f"((d)[1]), "+f"((d)[2]), "+f"((d)[3]) \
        : "r"((a)[0]), "r"((a)[1]), "r"((a)[2]), "r"((a)[3]), "r"((b)[0]), "r"((b)[1]))

#define MMA16816_INIT(d, a, b) \
    asm volatile("mma.sync.aligned.m16n8k16.row.col.f32.f16.f16.f32 " \
        "{%0,%1,%2,%3},{%4,%5,%6,%7},{%8,%9},{%10,%10,%10,%10};" \
        : "=f"((d)[0]), "=f"((d)[1]), "=f"((d)[2]), "=f"((d)[3]) \
        : "r"((a)[0]), "r"((a)[1]), "r"((a)[2]), "r"((a)[3]), "r"((b)[0]), "r"((b)[1]), \
          "f"(0.0f))

// ---------------------------------------------------------------------------
// Prep A: round inputs to fp16.  One warp per row.
// ---------------------------------------------------------------------------
__global__ void vq_prep_a(const float* __restrict__ X) {
    int w = threadIdx.x >> 5, lane = threadIdx.x & 31;
    int row = blockIdx.x * 8 + w;
    const float* x = X + (size_t)row * D_DIM;
    __half* a = g_Ah + (size_t)row * D_DIM;
#pragma unroll
    for (int i = 0; i < 8; i++) {
        int c = lane + 32 * i;
        a[c] = __float2half_rn(x[c]);
    }
}

// ---------------------------------------------------------------------------
// Prep B: fp16 codebook + fp32 half-norms; zero counters (replay-safe).
// ---------------------------------------------------------------------------
__global__ void vq_prep_b(const float* __restrict__ C) {
    int w = threadIdx.x >> 5, lane = threadIdx.x & 31;
    int row = blockIdx.x * 8 + w;
    const float* c = C + (size_t)row * D_DIM;
    __half* b = g_Bh + (size_t)row * D_DIM;
    float s = 0.f;
#pragma unroll
    for (int i = 0; i < 8; i++) {
        int k = lane + 32 * i;
        float v = c[k];
        s += v * v;
        b[k] = __float2half_rn(v);
    }
    s = warpReduceSum(s);
    if (lane == 0) g_cnorm[row] = 0.5f * s;
    if (blockIdx.x < K_CODES / 256) g_counts[blockIdx.x * 256 + threadIdx.x] = 0;
    if (blockIdx.x == 0 && threadIdx.x == 0) { g_loss = 0.0; g_unitCtr = 0; }
}

// ---------------------------------------------------------------------------
// Main: persistent 128-thread CTAs (3 per SM) pull (64-row, 1024-code) units.
// Resident A in smem; B through a 3-stage cp.async pipeline; fp16 HMMA;
// per-row top-2 (score+idx) over each eighth.  4 warps across N (tile 64x32).
// ---------------------------------------------------------------------------
__global__ void __launch_bounds__(128, 3) vq_main() {
    extern __shared__ char smem[];
    const uint32_t sbase = smem_to_u32(smem);
    float* sB1 = (float*)(smem + A_RES_B + SMEM_B);
    int*   sI1 = (int*)  (smem + A_RES_B + SMEM_B + 1024);
    float* sB2 = (float*)(smem + A_RES_B + SMEM_B + 2048);
    int*   sI2 = (int*)  (smem + A_RES_B + SMEM_B + 3072);
    __shared__ int sU;

    const int tid    = threadIdx.x;
    const int lane   = tid & 31;
    const int warp_n = tid >> 5;       // 0..3, cols warp_n*32
    const int l15    = lane & 15;
    const int colq   = (lane & 3) * 2;

    const uint32_t aOff = (uint32_t)((lane & 15) * APAD_B + ((lane >> 4) * 8) * 2);
    const uint32_t bOff = (uint32_t)((warp_n * 32 + (l15 & 7)) * (PADK * 2) + ((l15 >> 3) * 8) * 2);

    while (true) {
        CP_WAITALL();
        __syncthreads();
        if (tid == 0) sU = atomicAdd(&g_unitCtr, 1);
        __syncthreads();
        const int u = sU;
        if (u >= NUNITS) break;
        const int rowBase  = (u >> 3) * 64;
        const int e        = u & 7;
        const int codeBase = e * ECODES;

        // ---- B producer: 4 cp.async per thread per 32-K chunk ----
        auto issue_load = [&](int g) {
            if (g < CHUNKS_U) {
                int ct = g >> 3, kc = g & 7, st = g % NST;
                uint32_t sb = sbase + A_RES_B + st * B_ST;
                int kbase = kc * 32;
#pragma unroll
                for (int r = 0; r < 4; r++) {
                    int id = tid + 128 * r;    // 0..511
                    int row = id >> 2, seg = id & 3;
                    uint32_t so = sb + row * (PADK * 2) + seg * 16;
                    const __half* gp = g_Bh + (size_t)(codeBase + ct * 128 + row) * D_DIM + kbase + seg * 8;
                    CP_ASYNC16(so, gp);
                }
            }
            CP_COMMIT();
        };

        // resident A: 64 rows x 512B = 2048 x 16B; committed with chunk 0
#pragma unroll
        for (int r = 0; r < 16; r++) {
            int i = tid + 128 * r;             // 0..2047
            int row = i >> 5, seg = i & 31;
            CP_ASYNC16(sbase + row * APAD_B + seg * 16,
                       g_Ah + (size_t)(rowBase + row) * D_DIM + seg * 8);
        }
        issue_load(0);                          // group {A + chunk0}
        issue_load(1);                          // group {chunk1}

        float b1[8], b2[8];
        int   i1[8], i2[8];
#pragma unroll
        for (int r = 0; r < 8; r++) { b1[r] = b2[r] = -INFINITY; i1[r] = 0; i2[r] = 1; }

        float acc[4][4][4];

        auto do_chunk = [&](int gg, int kc, bool first) {
            CP_WAIT1();
            __syncthreads();
            issue_load(gg + 2);                 // stage (gg+2)%3 != gg%3
            uint32_t stg = sbase + A_RES_B + (uint32_t)(gg % NST) * B_ST;
            uint32_t aCk = sbase + aOff + kc * 64;
#pragma unroll
            for (int ks = 0; ks < 2; ks++) {
                uint32_t areg[4][4], breg[4][2];
#pragma unroll
                for (int i = 0; i < 4; i++)
                    LDSM_X4(areg[i][0], areg[i][1], areg[i][2], areg[i][3],
                            aCk + i * (16 * APAD_B) + ks * 32);
#pragma unroll
                for (int j = 0; j < 4; j++)
                    LDSM_X2(breg[j][0], breg[j][1],
                            stg + bOff + j * (8 * PADK * 2) + ks * 32);
                if (first && ks == 0) {
#pragma unroll
                    for (int i = 0; i < 4; i++)
#pragma unroll
                        for (int j = 0; j < 4; j++)
                            MMA16816_INIT(acc[i][j], areg[i], breg[j]);
                } else {
#pragma unroll
                    for (int i = 0; i < 4; i++)
#pragma unroll
                        for (int j = 0; j < 4; j++)
                            MMA16816(acc[i][j], areg[i], breg[j]);
                }
            }
        };

        for (int ct = 0; ct < NTILE_U; ct++) {
            float cnv[8];
#pragma unroll
            for (int j = 0; j < 4; j++) {
                float2 t = *(const float2*)&g_cnorm[codeBase + ct * 128 + warp_n * 32 + j * 8 + colq];
                cnv[2 * j] = t.x; cnv[2 * j + 1] = t.y;
            }

            do_chunk(ct * KCHUNK, 0, true);
#pragma unroll 1
            for (int kc = 1; kc < KCHUNK; kc++)
                do_chunk(ct * KCHUNK + kc, kc, false);

            // epilogue: branchless common path, rare exact fixup
#pragma unroll
            for (int j = 0; j < 4; j++) {
                int col = codeBase + ct * 128 + warp_n * 32 + j * 8 + colq;
                float cx = cnv[2 * j], cy = cnv[2 * j + 1];
#pragma unroll
                for (int i = 0; i < 4; i++) {
#pragma unroll
                    for (int h = 0; h < 2; h++) {
                        int r = i * 2 + h;
                        float s0 = acc[i][j][h * 2 + 0] - cx;
                        float s1 = acc[i][j][h * 2 + 1] - cy;
                        float m = fmaxf(s0, s1);
                        if (m > b2[r]) {
                            if (s0 > b1[r]) { b2[r] = b1[r]; i2[r] = i1[r]; b1[r] = s0; i1[r] = col; }
                            else if (s0 > b2[r]) { b2[r] = s0; i2[r] = col; }
                            if (s1 > b1[r]) { b2[r] = b1[r]; i2[r] = i1[r]; b1[r] = s1; i1[r] = col + 1; }
                            else if (s1 > b2[r]) { b2[r] = s1; i2[r] = col + 1; }
                        }
                    }
                }
            }
        }

        // ---- unit-end reduce: 4 col-lanes, then across the 4 N-warps ----
#pragma unroll
        for (int r = 0; r < 8; r++) {
            float a1 = b1[r], a2 = b2[r];
            int   x1 = i1[r], x2 = i2[r];
#pragma unroll
            for (int off = 1; off <= 2; off <<= 1) {
                float o1 = __shfl_xor_sync(0xffffffffu, a1, off);
                int   y1 = __shfl_xor_sync(0xffffffffu, x1, off);
                float o2 = __shfl_xor_sync(0xffffffffu, a2, off);
                int   y2 = __shfl_xor_sync(0xffffffffu, x2, off);
                if (o1 > a1 || (o1 == a1 && y1 < x1)) {
                    if (a1 > o2 || (a1 == o2 && x1 < y2)) { a2 = a1; x2 = x1; }
                    else { a2 = o2; x2 = y2; }
                    a1 = o1; x1 = y1;
                } else {
                    if (o1 > a2 || (o1 == a2 && y1 < x2)) { a2 = o1; x2 = y1; }
                }
            }
            if ((lane & 3) == 0) {
                int i = r >> 1, h = r & 1;
                int row = i * 16 + h * 8 + (lane >> 2);
                sB1[row * 4 + warp_n] = a1; sI1[row * 4 + warp_n] = x1;
                sB2[row * 4 + warp_n] = a2; sI2[row * 4 + warp_n] = x2;
            }
        }
        __syncthreads();
        if (tid < 64) {
            float a1 = sB1[tid * 4], a2 = sB2[tid * 4];
            int   x1 = sI1[tid * 4], x2 = sI2[tid * 4];
#pragma unroll
            for (int w = 1; w < 4; w++) {
                float o1 = sB1[tid * 4 + w], o2 = sB2[tid * 4 + w];
                int   y1 = sI1[tid * 4 + w], y2 = sI2[tid * 4 + w];
                if (o1 > a1 || (o1 == a1 && y1 < x1)) {
                    if (a1 > o2 || (a1 == o2 && x1 < y2)) { a2 = a1; x2 = x1; }
                    else { a2 = o2; x2 = y2; }
                    a1 = o1; x1 = y1;
                } else {
                    if (o1 > a2 || (o1 == a2 && y1 < x2)) { a2 = o1; x2 = y1; }
                }
            }
            int gr = rowBase + tid;
            g_c1[e * N_ROWS + gr] = x1; g_s1[e * N_ROWS + gr] = a1;
            g_c2[e * N_ROWS + gr] = x2; g_s2[e * N_ROWS + gr] = a2;
        }
    }
}

// ---------------------------------------------------------------------------
// Rescore + gather: one warp per row.  Approx max over the 16 candidates;
// only candidates within TAU of it get an exact fp32 dot (usually just one,
// so the common path is a pure gather).  Then ST output, token, count, loss.
// ---------------------------------------------------------------------------
__global__ void vq_rescore(const float* __restrict__ X, const float* __restrict__ C,
                           float* __restrict__ outQ, float* __restrict__ outTok) {
    int w = threadIdx.x >> 5, lane = threadIdx.x & 31;
    int row = blockIdx.x * 8 + w;

    float s = -INFINITY; int ci = 0;
    if (lane < 8)       { s = g_s1[lane * N_ROWS + row];       ci = g_c1[lane * N_ROWS + row]; }
    else if (lane < 16) { s = g_s2[(lane - 8) * N_ROWS + row]; ci = g_c2[(lane - 8) * N_ROWS + row]; }

    float m = s;
#pragma unroll
    for (int o = 16; o > 0; o >>= 1) m = fmaxf(m, __shfl_xor_sync(0xffffffffu, m, o));
    unsigned pass = __ballot_sync(0xffffffffu, s >= m - TAU);

    const float4* xp = (const float4*)(X + (size_t)row * D_DIM);
    float4 xa = xp[lane * 2], xb = xp[lane * 2 + 1];

    int winner;
    if (__popc(pass) == 1) {
        winner = __shfl_sync(0xffffffffu, ci, __ffs(pass) - 1);
    } else {
        float best = -INFINITY;
        int   bi   = 1 << 30;
        unsigned p = pass;
        while (p) {
            int src = __ffs(p) - 1; p &= p - 1;
            int cand = __shfl_sync(0xffffffffu, ci, src);
            const float4* cp = (const float4*)(C + (size_t)cand * D_DIM);
            float4 qa = cp[lane * 2], qb = cp[lane * 2 + 1];
            float d = xa.x * qa.x + xa.y * qa.y + xa.z * qa.z + xa.w * qa.w
                    + xb.x * qb.x + xb.y * qb.y + xb.z * qb.z + xb.w * qb.w;
            d = warpReduceSum(d);
            float sc = d - g_cnorm[cand];
            if (sc > best || (sc == best && cand < bi)) { best = sc; bi = cand; }
        }
        winner = bi;
    }

    // gather winner row, write straight-through output
    const float4* cw = (const float4*)(C + (size_t)winner * D_DIM);
    float4 qa = cw[lane * 2], qb = cw[lane * 2 + 1];
    float dax = qa.x - xa.x, day = qa.y - xa.y, daz = qa.z - xa.z, daw = qa.w - xa.w;
    float dbx = qb.x - xb.x, dby = qb.y - xb.y, dbz = qb.z - xb.z, dbw = qb.w - xb.w;
    float4* op = (float4*)(outQ + (size_t)row * D_DIM);
    op[lane * 2]     = make_float4(xa.x + dax, xa.y + day, xa.z + daz, xa.w + daw);
    op[lane * 2 + 1] = make_float4(xb.x + dbx, xb.y + dby, xb.z + dbz, xb.w + dbw);

    if (lane == 0) {
        outTok[row] = (float)winner;
        atomicAdd(&g_counts[winner], 1);
    }

    float sl = dax * dax + day * day + daz * daz + daw * daw
             + dbx * dbx + dby * dby + dbz * dbz + dbw * dbw;
    sl = warpReduceSum(sl);
    __shared__ float ps[8];
    if (lane == 0) ps[w] = sl;
    __syncthreads();
    if (w == 0) {
        float v = (lane < 8) ? ps[lane] : 0.f;
        v = warpReduceSum(v);
        if (lane == 0) atomicAdd(&g_loss, (double)v);
    }
}

// ---------------------------------------------------------------------------
// Finalize: losses + perplexity (1024 threads)
// ---------------------------------------------------------------------------
__global__ void vq_fin(float* __restrict__ outScal) {
    double ent = 0.0;
    float invN = 1.0f / (float)N_ROWS;
    for (int k = threadIdx.x; k < K_CODES; k += 1024) {
        float p = (float)g_counts[k] * invN;
        ent += (double)(p * logf(p + 1e-10f));
    }
    __shared__ double ds[1024];
    ds[threadIdx.x] = ent;
    __syncthreads();
    for (int s = 512; s > 0; s >>= 1) {
        if (threadIdx.x < s) ds[threadIdx.x] += ds[threadIdx.x + s];
        __syncthreads();
    }
    if (threadIdx.x == 0) {
        float perp = expf(-(float)ds[0]);
        double l = g_loss / ((double)N_ROWS * (double)D_DIM);
        float lf = (float)l;
        outScal[0] = 1.25f * lf;   // vq_loss
        outScal[1] = 0.25f * lf;   // commitment_loss
        outScal[2] = lf;           // codebook_loss
        outScal[3] = perp;         // perplexity
    }
}

// ---------------------------------------------------------------------------
extern "C" void kernel_launch(void* const* d_in, const int* in_sizes, int n_in,
                              void* d_out, int out_size) {
    const float* X = (const float*)d_in[0];   // [32,1024,256] f32
    const float* C = (const float*)d_in[1];   // [8192,256]    f32
    float* out = (float*)d_out;

    float* outTok  = out + (size_t)N_ROWS * D_DIM;
    float* outScal = outTok + N_ROWS;

    cudaFuncSetAttribute(vq_main, cudaFuncAttributeMaxDynamicSharedMemorySize, SMEM_TOTAL);

    vq_prep_b<<<K_CODES / 8, 256>>>(C);
    vq_prep_a<<<N_ROWS / 8, 256>>>(X);
    vq_main<<<456, 128, SMEM_TOTAL>>>();      // persistent, 3 CTAs/SM target
    vq_rescore<<<N_ROWS / 8, 256>>>(X, C, out, outTok);
    vq_fin<<<1, 1024>>>(outScal);
}

// round 16
// speedup vs baseline: 7.0434x; 1.0251x over previous
#include <cuda_runtime.h>
#include <cuda_fp16.h>
#include <math.h>
#include <stdint.h>

// Problem sizes (fixed for this dataset)
#define N_ROWS  32768
#define K_CODES 8192
#define D_DIM   256

// Work decomposition: unit = (64-row tile) x (1024-code eighth)
#define NEIGHTH  8
#define ECODES   1024
#define NUNITS   ((N_ROWS / 64) * NEIGHTH)   // 4096
#define NTILE_U  (ECODES / 128)              // 8 col-tiles of 128 per unit
#define KCHUNK   8                           // 256 K / 32
#define CHUNKS_U (NTILE_U * KCHUNK)          // 64

// smem: resident A (64 rows) + 3-stage B pipeline + reduce scratch
#define APAD_B  528                          // A row stride bytes (512 data + 16)
#define A_RES_B (64 * APAD_B)                // 33792
#define PADK    40                           // B smem row: 32 fp16 + 8 pad = 80B
#define B_ST    (128 * PADK * 2)             // 10240
#define NST     3
#define SMEM_B  (NST * B_ST)                 // 30720
#define SMEM_RED 4096
#define SMEM_TOTAL (A_RES_B + SMEM_B + SMEM_RED)   // 68608

#define TAU 0.08f                            // rescore margin (fp16 noise ~6e-3)

// -------- scratch (no allocations allowed) --------
__device__ int    g_c1[NEIGHTH * N_ROWS];
__device__ int    g_c2[NEIGHTH * N_ROWS];
__device__ float  g_s1[NEIGHTH * N_ROWS];
__device__ float  g_s2[NEIGHTH * N_ROWS];
__device__ int    g_counts[K_CODES];
__device__ float  g_cnorm[K_CODES];             // 0.5*||c||^2 (fp32)
__device__ double g_loss;
__device__ int    g_unitCtr;
__device__ __half g_Ah[(size_t)N_ROWS * D_DIM]; // 16.8 MB
__device__ __half g_Bh[(size_t)K_CODES * D_DIM];// 4.2 MB

// ======================= helpers =======================
__device__ __forceinline__ uint32_t smem_to_u32(const void* p) {
    uint32_t a;
    asm("{ .reg .u64 t; cvta.to.shared.u64 t, %1; cvt.u32.u64 %0, t; }" : "=r"(a) : "l"(p));
    return a;
}
__device__ __forceinline__ float warpReduceSum(float v) {
#pragma unroll
    for (int o = 16; o > 0; o >>= 1) v += __shfl_xor_sync(0xffffffffu, v, o);
    return v;
}

#define CP_ASYNC16(smem_u32, gptr) \
    asm volatile("cp.async.cg.shared.global [%0], [%1], 16;" :: "r"(smem_u32), "l"(gptr) : "memory")
#define CP_COMMIT()  asm volatile("cp.async.commit_group;" ::: "memory")
#define CP_WAIT1()   asm volatile("cp.async.wait_group 1;" ::: "memory")
#define CP_WAITALL() asm volatile("cp.async.wait_all;" ::: "memory")

#define LDSM_X4(r0, r1, r2, r3, addr) \
    asm volatile("ldmatrix.sync.aligned.m8n8.x4.shared.b16 {%0,%1,%2,%3}, [%4];" \
        : "=r"(r0), "=r"(r1), "=r"(r2), "=r"(r3) : "r"(addr))

#define MMA16816(d, a, b) \
    asm volatile("mma.sync.aligned.m16n8k16.row.col.f32.f16.f16.f32 " \
        "{%0,%1,%2,%3},{%4,%5,%6,%7},{%8,%9},{%0,%1,%2,%3};" \
        : "+f"((d)[0]), "+f"((d)[1]), "+f"((d)[2]), "+f"((d)[3]) \
        : "r"((a)[0]), "r"((a)[1]), "r"((a)[2]), "r"((a)[3]), "r"((b)[0]), "r"((b)[1]))

#define MMA16816_INIT(d, a, b) \
    asm volatile("mma.sync.aligned.m16n8k16.row.col.f32.f16.f16.f32 " \
        "{%0,%1,%2,%3},{%4,%5,%6,%7},{%8,%9},{%10,%10,%10,%10};" \
        : "=f"((d)[0]), "=f"((d)[1]), "=f"((d)[2]), "=f"((d)[3]) \
        : "r"((a)[0]), "r"((a)[1]), "r"((a)[2]), "r"((a)[3]), "r"((b)[0]), "r"((b)[1]), \
          "f"(0.0f))

// ---------------------------------------------------------------------------
// Prep (merged): blocks [0,4096) convert X rows; blocks [4096,5120) convert
// codebook rows + half-norms; counters zeroed (replay-safe).
// ---------------------------------------------------------------------------
__global__ void vq_prep(const float* __restrict__ X, const float* __restrict__ C) {
    int w = threadIdx.x >> 5, lane = threadIdx.x & 31;
    if (blockIdx.x < N_ROWS / 8) {
        int row = blockIdx.x * 8 + w;
        const float* x = X + (size_t)row * D_DIM;
        __half* a = g_Ah + (size_t)row * D_DIM;
#pragma unroll
        for (int i = 0; i < 8; i++) {
            int c = lane + 32 * i;
            a[c] = __float2half_rn(x[c]);
        }
    } else {
        int bb = blockIdx.x - N_ROWS / 8;
        int row = bb * 8 + w;
        const float* c = C + (size_t)row * D_DIM;
        __half* b = g_Bh + (size_t)row * D_DIM;
        float s = 0.f;
#pragma unroll
        for (int i = 0; i < 8; i++) {
            int k = lane + 32 * i;
            float v = c[k];
            s += v * v;
            b[k] = __float2half_rn(v);
        }
        s = warpReduceSum(s);
        if (lane == 0) g_cnorm[row] = 0.5f * s;
        if (bb < K_CODES / 256) g_counts[bb * 256 + threadIdx.x] = 0;
        if (bb == 0 && threadIdx.x == 0) { g_loss = 0.0; g_unitCtr = 0; }
    }
}

// ---------------------------------------------------------------------------
// Main: persistent 128-thread CTAs (3 per SM) pull (64-row, 1024-code) units.
// Resident A in smem; B through a 3-stage cp.async pipeline; fp16 HMMA;
// per-row top-2 (score+idx) over each eighth.  4 warps across N (tile 64x32).
// B fragments via ldmatrix.x4: one instr covers a j-pair (both k-segments).
// ---------------------------------------------------------------------------
__global__ void __launch_bounds__(128, 3) vq_main() {
    extern __shared__ char smem[];
    const uint32_t sbase = smem_to_u32(smem);
    float* sB1 = (float*)(smem + A_RES_B + SMEM_B);
    int*   sI1 = (int*)  (smem + A_RES_B + SMEM_B + 1024);
    float* sB2 = (float*)(smem + A_RES_B + SMEM_B + 2048);
    int*   sI2 = (int*)  (smem + A_RES_B + SMEM_B + 3072);
    __shared__ int sU;

    const int tid    = threadIdx.x;
    const int lane   = tid & 31;
    const int warp_n = tid >> 5;       // 0..3, cols warp_n*32
    const int colq   = (lane & 3) * 2;

    const uint32_t aOff = (uint32_t)((lane & 15) * APAD_B + ((lane >> 4) * 8) * 2);
    // x4 B mapping: matrices (j0,k0),(j0,k1),(j1,k0),(j1,k1) from lane octets
    const uint32_t bOff4 = (uint32_t)((warp_n * 32 + ((lane >> 4) & 1) * 8 + (lane & 7)) * (PADK * 2)
                                      + ((lane >> 3) & 1) * 16);

    while (true) {
        CP_WAITALL();
        __syncthreads();
        if (tid == 0) sU = atomicAdd(&g_unitCtr, 1);
        __syncthreads();
        const int u = sU;
        if (u >= NUNITS) break;
        const int rowBase  = (u >> 3) * 64;
        const int e        = u & 7;
        const int codeBase = e * ECODES;

        // ---- B producer: 4 cp.async per thread per 32-K chunk ----
        auto issue_load = [&](int g) {
            if (g < CHUNKS_U) {
                int ct = g >> 3, kc = g & 7, st = g % NST;
                uint32_t sb = sbase + A_RES_B + st * B_ST;
                int kbase = kc * 32;
#pragma unroll
                for (int r = 0; r < 4; r++) {
                    int id = tid + 128 * r;    // 0..511
                    int row = id >> 2, seg = id & 3;
                    uint32_t so = sb + row * (PADK * 2) + seg * 16;
                    const __half* gp = g_Bh + (size_t)(codeBase + ct * 128 + row) * D_DIM + kbase + seg * 8;
                    CP_ASYNC16(so, gp);
                }
            }
            CP_COMMIT();
        };

        // resident A: 64 rows x 512B = 2048 x 16B; committed with chunk 0
#pragma unroll
        for (int r = 0; r < 16; r++) {
            int i = tid + 128 * r;             // 0..2047
            int row = i >> 5, seg = i & 31;
            CP_ASYNC16(sbase + row * APAD_B + seg * 16,
                       g_Ah + (size_t)(rowBase + row) * D_DIM + seg * 8);
        }
        issue_load(0);                          // group {A + chunk0}
        issue_load(1);                          // group {chunk1}

        float b1[8], b2[8];
        int   i1[8], i2[8];
#pragma unroll
        for (int r = 0; r < 8; r++) { b1[r] = b2[r] = -INFINITY; i1[r] = 0; i2[r] = 1; }

        float acc[4][4][4];

        auto do_chunk = [&](int gg, int kc, bool first) {
            CP_WAIT1();
            __syncthreads();
            issue_load(gg + 2);                 // stage (gg+2)%3 != gg%3
            uint32_t stg = sbase + A_RES_B + (uint32_t)(gg % NST) * B_ST;
            uint32_t aCk = sbase + aOff + kc * 64;
#pragma unroll
            for (int ks = 0; ks < 2; ks++) {
                uint32_t areg[4][4], breg[4][2];
#pragma unroll
                for (int i = 0; i < 4; i++)
                    LDSM_X4(areg[i][0], areg[i][1], areg[i][2], areg[i][3],
                            aCk + i * (16 * APAD_B) + ks * 32);
#pragma unroll
                for (int jp = 0; jp < 2; jp++)  // j-pair: tiles {2jp, 2jp+1}
                    LDSM_X4(breg[2 * jp][0], breg[2 * jp][1],
                            breg[2 * jp + 1][0], breg[2 * jp + 1][1],
                            stg + bOff4 + jp * (16 * PADK * 2) + ks * 32);
                if (first && ks == 0) {
#pragma unroll
                    for (int i = 0; i < 4; i++)
#pragma unroll
                        for (int j = 0; j < 4; j++)
                            MMA16816_INIT(acc[i][j], areg[i], breg[j]);
                } else {
#pragma unroll
                    for (int i = 0; i < 4; i++)
#pragma unroll
                        for (int j = 0; j < 4; j++)
                            MMA16816(acc[i][j], areg[i], breg[j]);
                }
            }
        };

        for (int ct = 0; ct < NTILE_U; ct++) {
            float cnv[8];
#pragma unroll
            for (int j = 0; j < 4; j++) {
                float2 t = *(const float2*)&g_cnorm[codeBase + ct * 128 + warp_n * 32 + j * 8 + colq];
                cnv[2 * j] = t.x; cnv[2 * j + 1] = t.y;
            }

            do_chunk(ct * KCHUNK, 0, true);
#pragma unroll 1
            for (int kc = 1; kc < KCHUNK; kc++)
                do_chunk(ct * KCHUNK + kc, kc, false);

            // epilogue: branchless common path, rare exact fixup
#pragma unroll
            for (int j = 0; j < 4; j++) {
                int col = codeBase + ct * 128 + warp_n * 32 + j * 8 + colq;
                float cx = cnv[2 * j], cy = cnv[2 * j + 1];
#pragma unroll
                for (int i = 0; i < 4; i++) {
#pragma unroll
                    for (int h = 0; h < 2; h++) {
                        int r = i * 2 + h;
                        float s0 = acc[i][j][h * 2 + 0] - cx;
                        float s1 = acc[i][j][h * 2 + 1] - cy;
                        float m = fmaxf(s0, s1);
                        if (m > b2[r]) {
                            if (s0 > b1[r]) { b2[r] = b1[r]; i2[r] = i1[r]; b1[r] = s0; i1[r] = col; }
                            else if (s0 > b2[r]) { b2[r] = s0; i2[r] = col; }
                            if (s1 > b1[r]) { b2[r] = b1[r]; i2[r] = i1[r]; b1[r] = s1; i1[r] = col + 1; }
                            else if (s1 > b2[r]) { b2[r] = s1; i2[r] = col + 1; }
                        }
                    }
                }
            }
        }

        // ---- unit-end reduce: 4 col-lanes, then across the 4 N-warps ----
#pragma unroll
        for (int r = 0; r < 8; r++) {
            float a1 = b1[r], a2 = b2[r];
            int   x1 = i1[r], x2 = i2[r];
#pragma unroll
            for (int off = 1; off <= 2; off <<= 1) {
                float o1 = __shfl_xor_sync(0xffffffffu, a1, off);
                int   y1 = __shfl_xor_sync(0xffffffffu, x1, off);
                float o2 = __shfl_xor_sync(0xffffffffu, a2, off);
                int   y2 = __shfl_xor_sync(0xffffffffu, x2, off);
                if (o1 > a1 || (o1 == a1 && y1 < x1)) {
                    if (a1 > o2 || (a1 == o2 && x1 < y2)) { a2 = a1; x2 = x1; }
                    else { a2 = o2; x2 = y2; }
                    a1 = o1; x1 = y1;
                } else {
                    if (o1 > a2 || (o1 == a2 && y1 < x2)) { a2 = o1; x2 = y1; }
                }
            }
            if ((lane & 3) == 0) {
                int i = r >> 1, h = r & 1;
                int row = i * 16 + h * 8 + (lane >> 2);
                sB1[row * 4 + warp_n] = a1; sI1[row * 4 + warp_n] = x1;
                sB2[row * 4 + warp_n] = a2; sI2[row * 4 + warp_n] = x2;
            }
        }
        __syncthreads();
        if (tid < 64) {
            float a1 = sB1[tid * 4], a2 = sB2[tid * 4];
            int   x1 = sI1[tid * 4], x2 = sI2[tid * 4];
#pragma unroll
            for (int w = 1; w < 4; w++) {
                float o1 = sB1[tid * 4 + w], o2 = sB2[tid * 4 + w];
                int   y1 = sI1[tid * 4 + w], y2 = sI2[tid * 4 + w];
                if (o1 > a1 || (o1 == a1 && y1 < x1)) {
                    if (a1 > o2 || (a1 == o2 && x1 < y2)) { a2 = a1; x2 = x1; }
                    else { a2 = o2; x2 = y2; }
                    a1 = o1; x1 = y1;
                } else {
                    if (o1 > a2 || (o1 == a2 && y1 < x2)) { a2 = o1; x2 = y1; }
                }
            }
            int gr = rowBase + tid;
            g_c1[e * N_ROWS + gr] = x1; g_s1[e * N_ROWS + gr] = a1;
            g_c2[e * N_ROWS + gr] = x2; g_s2[e * N_ROWS + gr] = a2;
        }
    }
}

// ---------------------------------------------------------------------------
// Rescore + gather: one warp per row.  Approx max over the 16 candidates;
// only candidates within TAU of it get an exact fp32 dot (usually just one,
// so the common path is a pure gather).  Then ST output, token, count, loss.
// ---------------------------------------------------------------------------
__global__ void vq_rescore(const float* __restrict__ X, const float* __restrict__ C,
                           float* __restrict__ outQ, float* __restrict__ outTok) {
    int w = threadIdx.x >> 5, lane = threadIdx.x & 31;
    int row = blockIdx.x * 8 + w;

    float s = -INFINITY; int ci = 0;
    if (lane < 8)       { s = g_s1[lane * N_ROWS + row];       ci = g_c1[lane * N_ROWS + row]; }
    else if (lane < 16) { s = g_s2[(lane - 8) * N_ROWS + row]; ci = g_c2[(lane - 8) * N_ROWS + row]; }

    float m = s;
#pragma unroll
    for (int o = 16; o > 0; o >>= 1) m = fmaxf(m, __shfl_xor_sync(0xffffffffu, m, o));
    unsigned pass = __ballot_sync(0xffffffffu, s >= m - TAU);

    const float4* xp = (const float4*)(X + (size_t)row * D_DIM);
    float4 xa = xp[lane * 2], xb = xp[lane * 2 + 1];

    int winner;
    if (__popc(pass) == 1) {
        winner = __shfl_sync(0xffffffffu, ci, __ffs(pass) - 1);
    } else {
        float best = -INFINITY;
        int   bi   = 1 << 30;
        unsigned p = pass;
        while (p) {
            int src = __ffs(p) - 1; p &= p - 1;
            int cand = __shfl_sync(0xffffffffu, ci, src);
            const float4* cp = (const float4*)(C + (size_t)cand * D_DIM);
            float4 qa = cp[lane * 2], qb = cp[lane * 2 + 1];
            float d = xa.x * qa.x + xa.y * qa.y + xa.z * qa.z + xa.w * qa.w
                    + xb.x * qb.x + xb.y * qb.y + xb.z * qb.z + xb.w * qb.w;
            d = warpReduceSum(d);
            float sc = d - g_cnorm[cand];
            if (sc > best || (sc == best && cand < bi)) { best = sc; bi = cand; }
        }
        winner = bi;
    }

    // gather winner row, write straight-through output
    const float4* cw = (const float4*)(C + (size_t)winner * D_DIM);
    float4 qa = cw[lane * 2], qb = cw[lane * 2 + 1];
    float dax = qa.x - xa.x, day = qa.y - xa.y, daz = qa.z - xa.z, daw = qa.w - xa.w;
    float dbx = qb.x - xb.x, dby = qb.y - xb.y, dbz = qb.z - xb.z, dbw = qb.w - xb.w;
    float4* op = (float4*)(outQ + (size_t)row * D_DIM);
    op[lane * 2]     = make_float4(xa.x + dax, xa.y + day, xa.z + daz, xa.w + daw);
    op[lane * 2 + 1] = make_float4(xb.x + dbx, xb.y + dby, xb.z + dbz, xb.w + dbw);

    if (lane == 0) {
        outTok[row] = (float)winner;
        atomicAdd(&g_counts[winner], 1);
    }

    float sl = dax * dax + day * day + daz * daz + daw * daw
             + dbx * dbx + dby * dby + dbz * dbz + dbw * dbw;
    sl = warpReduceSum(sl);
    __shared__ float ps[8];
    if (lane == 0) ps[w] = sl;
    __syncthreads();
    if (w == 0) {
        float v = (lane < 8) ? ps[lane] : 0.f;
        v = warpReduceSum(v);
        if (lane == 0) atomicAdd(&g_loss, (double)v);
    }
}

// ---------------------------------------------------------------------------
// Finalize: losses + perplexity (1024 threads)
// ---------------------------------------------------------------------------
__global__ void vq_fin(float* __restrict__ outScal) {
    double ent = 0.0;
    float invN = 1.0f / (float)N_ROWS;
    for (int k = threadIdx.x; k < K_CODES; k += 1024) {
        float p = (float)g_counts[k] * invN;
        ent += (double)(p * logf(p + 1e-10f));
    }
    __shared__ double ds[1024];
    ds[threadIdx.x] = ent;
    __syncthreads();
    for (int s = 512; s > 0; s >>= 1) {
        if (threadIdx.x < s) ds[threadIdx.x] += ds[threadIdx.x + s];
        __syncthreads();
    }
    if (threadIdx.x == 0) {
        float perp = expf(-(float)ds[0]);
        double l = g_loss / ((double)N_ROWS * (double)D_DIM);
        float lf = (float)l;
        outScal[0] = 1.25f * lf;   // vq_loss
        outScal[1] = 0.25f * lf;   // commitment_loss
        outScal[2] = lf;           // codebook_loss
        outScal[3] = perp;         // perplexity
    }
}

// ---------------------------------------------------------------------------
extern "C" void kernel_launch(void* const* d_in, const int* in_sizes, int n_in,
                              void* d_out, int out_size) {
    const float* X = (const float*)d_in[0];   // [32,1024,256] f32
    const float* C = (const float*)d_in[1];   // [8192,256]    f32
    float* out = (float*)d_out;

    float* outTok  = out + (size_t)N_ROWS * D_DIM;
    float* outScal = outTok + N_ROWS;

    cudaFuncSetAttribute(vq_main, cudaFuncAttributeMaxDynamicSharedMemorySize, SMEM_TOTAL);

    vq_prep<<<N_ROWS / 8 + K_CODES / 8, 256>>>(X, C);
    vq_main<<<456, 128, SMEM_TOTAL>>>();      // persistent, 3 CTAs/SM
    vq_rescore<<<N_ROWS / 8, 256>>>(X, C, out, outTok);
    vq_fin<<<1, 1024>>>(outScal);
}